// round 5
// baseline (speedup 1.0000x reference)
#include <cuda_runtime.h>

#define HH 768
#define WW 768
#define NB 512
#define C1N 32
#define C2N 64
#define IW 769            // logical integral image height/width (H+1)
#define RS 772            // padded row stride (16B aligned)
#define FEAT 1600         // C2 * 5 * 5
#define FC1N 128
#define NCLS 4

// ---------------- scratch (no allocations allowed) ----------------
__device__ float g_buf1[C1N * HH * WW];        // conv1 output (32,768,768)
__device__ float g_integ[C2N * IW * RS];       // conv2 output -> integral image (64,769,772)
__device__ float g_flat[NB * FEAT];            // pooled features (512,1600)
__device__ float g_h1[NB * FC1N];              // fc1 output (512,128)

// ---------------- packed f32x2 helpers ----------------
typedef unsigned long long ull;

__device__ __forceinline__ ull ffma2(ull a, ull b, ull c) {
    ull d;
    asm("fma.rn.f32x2 %0, %1, %2, %3;" : "=l"(d) : "l"(a), "l"(b), "l"(c));
    return d;
}
__device__ __forceinline__ ull pack2(float lo, float hi) {
    ull r;
    asm("mov.b64 %0, {%1, %2};" : "=l"(r) : "f"(lo), "f"(hi));
    return r;
}
__device__ __forceinline__ void unpack2(ull v, float& lo, float& hi) {
    asm("mov.b64 {%0, %1}, %2;" : "=f"(lo), "=f"(hi) : "l"(v));
}

// ---------------- fused conv3x3 + bias + relu + bn ----------------
// Block: 32x4 threads. Tile: 32 wide x 16 tall. Each thread: 4 rows x OCC out-channels.
// Accumulators packed in f32x2 pairs along the OC dimension (FFMA2 = 2 MACs/slot).
template <int IC, int OCC>
__global__ __launch_bounds__(128)
void conv_bn_kernel(const float* __restrict__ in,
                    const float* __restrict__ wgt,   // [OC][IC][3][3]
                    const float* __restrict__ bias,
                    const float* __restrict__ bng,
                    const float* __restrict__ bnb,
                    const float* __restrict__ bnm,
                    const float* __restrict__ bnv,
                    float* __restrict__ out,
                    int rowStride, int chanStride, int outOff)
{
    extern __shared__ float smem[];
    float* s_in = smem;                 // [IC][18][34]
    float* s_w  = smem + IC * 18 * 34;  // [9][IC][OCC]  (oc consecutive -> LDS.64 pairs)

    const int tx = threadIdx.x, ty = threadIdx.y;
    const int tid = ty * 32 + tx;
    const int bx0 = blockIdx.x * 32;
    const int by0 = blockIdx.y * 16;
    const int ocBase = blockIdx.z * OCC;

    for (int idx = tid; idx < IC * 18 * 34; idx += 128) {
        int ic = idx / (18 * 34);
        int r  = idx % (18 * 34);
        int yy = r / 34, xx = r % 34;
        int gy = by0 + yy - 1, gx = bx0 + xx - 1;
        float v = 0.f;
        if (gy >= 0 && gy < HH && gx >= 0 && gx < WW)
            v = in[(ic * HH + gy) * WW + gx];
        s_in[idx] = v;
    }
    for (int idx = tid; idx < 9 * IC * OCC; idx += 128) {
        int tap = idx / (IC * OCC);
        int r   = idx % (IC * OCC);
        int ic  = r / OCC, oc = r % OCC;
        s_w[idx] = wgt[((ocBase + oc) * IC + ic) * 9 + tap];
    }
    __syncthreads();

    constexpr int OCP = OCC / 2;
    ull acc[OCP][4];
#pragma unroll
    for (int op = 0; op < OCP; ++op)
#pragma unroll
        for (int p = 0; p < 4; ++p) acc[op][p] = 0ull;

#pragma unroll 1
    for (int ic = 0; ic < IC; ++ic) {
#pragma unroll
        for (int tap = 0; tap < 9; ++tap) {
            const int ky = tap / 3, kx = tap % 3;
            ull vv[4];
#pragma unroll
            for (int p = 0; p < 4; ++p) {
                float v = s_in[(ic * 18 + (ty * 4 + p + ky)) * 34 + tx + kx];
                vv[p] = pack2(v, v);
            }
            const ull* wrow = (const ull*)&s_w[(tap * IC + ic) * OCC];
#pragma unroll
            for (int op = 0; op < OCP; ++op) {
                const ull w2 = wrow[op];
#pragma unroll
                for (int p = 0; p < 4; ++p)
                    acc[op][p] = ffma2(vv[p], w2, acc[op][p]);
            }
        }
    }

#pragma unroll
    for (int op = 0; op < OCP; ++op) {
#pragma unroll
        for (int half = 0; half < 2; ++half) {
            const int ocg = ocBase + op * 2 + half;
            const float b  = bias[ocg];
            const float sc = bng[ocg] / sqrtf(bnv[ocg] + 1e-5f);
            const float sh = bnb[ocg] - bnm[ocg] * sc;
#pragma unroll
            for (int p = 0; p < 4; ++p) {
                float lo, hi;
                unpack2(acc[op][p], lo, hi);
                float vv = (half ? hi : lo) + b;
                vv = vv > 0.f ? vv : 0.f;
                vv = vv * sc + sh;
                const int gy = by0 + ty * 4 + p;
                const int gx = bx0 + tx;
                out[ocg * chanStride + gy * rowStride + gx + outOff] = vv;
            }
        }
    }
}

// ---------------- integral image ----------------
// Pass 1: vertical serial cumsum (matches reference cumsum(axis=1) ordering).
// One thread per 4 columns (float4); 8-row chunks with all loads issued
// before accumulation -> MLP=8 per thread. Col 0 / pad cols zero-masked.
__global__ __launch_bounds__(64)
void vscan_kernel()
{
    const int t = blockIdx.x * 64 + threadIdx.x;   // 0..192 per channel
    if (t >= 193) return;
    const int c = blockIdx.y;
    const int x4 = t * 4;                           // column base (multiple of 4)
    float* base = g_integ + (size_t)c * IW * RS + x4;

    // zero-mask: component j valid iff 1 <= x4+j <= 768
    float4 mask;
    mask.x = (x4 + 0 >= 1 && x4 + 0 <= 768) ? 1.f : 0.f;
    mask.y = (x4 + 1 >= 1 && x4 + 1 <= 768) ? 1.f : 0.f;
    mask.z = (x4 + 2 >= 1 && x4 + 2 <= 768) ? 1.f : 0.f;
    mask.w = (x4 + 3 >= 1 && x4 + 3 <= 768) ? 1.f : 0.f;

    // top row zeros
    *(float4*)base = make_float4(0.f, 0.f, 0.f, 0.f);

    float4 run = make_float4(0.f, 0.f, 0.f, 0.f);
#pragma unroll 1
    for (int ch = 0; ch < 96; ++ch) {
        const int y0 = 1 + ch * 8;
        float4 v[8];
#pragma unroll
        for (int r = 0; r < 8; ++r)
            v[r] = *(const float4*)(base + (size_t)(y0 + r) * RS);
#pragma unroll
        for (int r = 0; r < 8; ++r) {
            run.x += v[r].x * mask.x;
            run.y += v[r].y * mask.y;
            run.z += v[r].z * mask.z;
            run.w += v[r].w * mask.w;
            *(float4*)(base + (size_t)(y0 + r) * RS) = run;
        }
    }
}

// Pass 2: horizontal cumsum. Warp per row; load ALL 24 chunks up front
// (MLP=24), then shuffle-scan + carry in registers, then store.
__global__ __launch_bounds__(256)
void hscan_kernel()
{
    const int warp = (blockIdx.x * blockDim.x + threadIdx.x) >> 5;
    const int lane = threadIdx.x & 31;
    if (warp >= C2N * HH) return;
    const int c = warp / HH;
    const int y = warp % HH + 1;
    float* row = g_integ + ((size_t)c * IW + y) * RS;

    float v[24];
#pragma unroll
    for (int k = 0; k < 24; ++k)
        v[k] = row[1 + k * 32 + lane];

    float carry = 0.f;
#pragma unroll
    for (int k = 0; k < 24; ++k) {
#pragma unroll
        for (int d = 1; d < 32; d <<= 1) {
            float n = __shfl_up_sync(0xFFFFFFFFu, v[k], d);
            if (lane >= d) v[k] += n;
        }
        v[k] += carry;
        carry = __shfl_sync(0xFFFFFFFFu, v[k], 31);
    }

#pragma unroll
    for (int k = 0; k < 24; ++k)
        row[1 + k * 32 + lane] = v[k];
}

// ---------------- ROI 5x5 pooling via integral image ----------------
__global__ void pool_kernel(const int* __restrict__ boxes)
{
    const int n = blockIdx.x;
    __shared__ int sy0[5], sy1[5], sx0[5], sx1[5];
    const int tid = threadIdx.x;
    if (tid < 5) {
        const int xmin = boxes[n * 4 + 0];
        const int ymin = boxes[n * 4 + 1];
        const int xmax = boxes[n * 4 + 2];
        const int ymax = boxes[n * 4 + 3];
        const int bh = ymax - ymin;
        const int bw = xmax - xmin;
        sy0[tid] = ymin + tid * bh / 5;
        sy1[tid] = ymin + ((tid + 1) * bh + 4) / 5;
        sx0[tid] = xmin + tid * bw / 5;
        sx1[tid] = xmin + ((tid + 1) * bw + 4) / 5;
    }
    __syncthreads();
    for (int e = tid; e < FEAT; e += blockDim.x) {
        const int c = e / 25, ij = e % 25, i = ij / 5, j = ij % 5;
        const float* I = g_integ + (size_t)c * IW * RS;
        const int y0 = sy0[i], y1 = sy1[i], x0 = sx0[j], x1 = sx1[j];
        const float s = I[(size_t)y1 * RS + x1] - I[(size_t)y0 * RS + x1]
                      - I[(size_t)y1 * RS + x0] + I[(size_t)y0 * RS + x0];
        const float area = (float)((y1 - y0) * (x1 - x0));
        g_flat[(size_t)n * FEAT + e] = s / area;
    }
}

// ---------------- fc1: (512,1600) @ (1600,128)^T + relu ----------------
__global__ __launch_bounds__(128)
void fc1_kernel(const float* __restrict__ w, const float* __restrict__ b)
{
    __shared__ float sf[4][FEAT];
    const int nb0 = blockIdx.x * 4;
    const int tid = threadIdx.x;
    for (int i = tid; i < 4 * FEAT; i += 128)
        sf[i / FEAT][i % FEAT] = g_flat[(size_t)(nb0 + i / FEAT) * FEAT + i % FEAT];
    __syncthreads();

    float acc0 = 0.f, acc1 = 0.f, acc2 = 0.f, acc3 = 0.f;
    const float* wr = w + (size_t)tid * FEAT;
    for (int k = 0; k < FEAT; k += 4) {
        const float4 wv = *(const float4*)(wr + k);
        acc0 += sf[0][k] * wv.x + sf[0][k + 1] * wv.y + sf[0][k + 2] * wv.z + sf[0][k + 3] * wv.w;
        acc1 += sf[1][k] * wv.x + sf[1][k + 1] * wv.y + sf[1][k + 2] * wv.z + sf[1][k + 3] * wv.w;
        acc2 += sf[2][k] * wv.x + sf[2][k + 1] * wv.y + sf[2][k + 2] * wv.z + sf[2][k + 3] * wv.w;
        acc3 += sf[3][k] * wv.x + sf[3][k + 1] * wv.y + sf[3][k + 2] * wv.z + sf[3][k + 3] * wv.w;
    }
    const float bb = b[tid];
    float r0 = acc0 + bb, r1 = acc1 + bb, r2 = acc2 + bb, r3 = acc3 + bb;
    g_h1[(size_t)(nb0 + 0) * FC1N + tid] = r0 > 0.f ? r0 : 0.f;
    g_h1[(size_t)(nb0 + 1) * FC1N + tid] = r1 > 0.f ? r1 : 0.f;
    g_h1[(size_t)(nb0 + 2) * FC1N + tid] = r2 > 0.f ? r2 : 0.f;
    g_h1[(size_t)(nb0 + 3) * FC1N + tid] = r3 > 0.f ? r3 : 0.f;
}

// ---------------- fc2: (512,128) @ (128,4)^T ----------------
__global__ void fc2_kernel(const float* __restrict__ w, const float* __restrict__ bias,
                           float* __restrict__ out)
{
    const int t = blockIdx.x * blockDim.x + threadIdx.x;
    if (t >= NB * NCLS) return;
    const int n = t / NCLS, o = t % NCLS;
    const float* h  = g_h1 + (size_t)n * FC1N;
    const float* wr = w + (size_t)o * FC1N;
    float acc = 0.f;
#pragma unroll 8
    for (int k = 0; k < FC1N; ++k) acc += h[k] * wr[k];
    out[t] = acc + bias[o];
}

// ---------------- launch ----------------
extern "C" void kernel_launch(void* const* d_in, const int* in_sizes, int n_in,
                              void* d_out, int out_size)
{
    const float* image  = (const float*)d_in[0];
    const int*   boxes  = (const int*)d_in[1];
    const float* c1w    = (const float*)d_in[2];
    const float* c1b    = (const float*)d_in[3];
    const float* bn1g   = (const float*)d_in[4];
    const float* bn1b   = (const float*)d_in[5];
    const float* bn1m   = (const float*)d_in[6];
    const float* bn1v   = (const float*)d_in[7];
    const float* c2w    = (const float*)d_in[8];
    const float* c2b    = (const float*)d_in[9];
    const float* bn2g   = (const float*)d_in[10];
    const float* bn2b   = (const float*)d_in[11];
    const float* bn2m   = (const float*)d_in[12];
    const float* bn2v   = (const float*)d_in[13];
    const float* fc1w   = (const float*)d_in[14];
    const float* fc1b   = (const float*)d_in[15];
    const float* fc2w   = (const float*)d_in[16];
    const float* fc2b   = (const float*)d_in[17];
    float* out = (float*)d_out;

    float *p_buf1, *p_integ;
    cudaGetSymbolAddress((void**)&p_buf1, g_buf1);
    cudaGetSymbolAddress((void**)&p_integ, g_integ);

    const int smem1 = (3 * 18 * 34 + 9 * 3 * 16) * 4;
    const int smem2 = (32 * 18 * 34 + 9 * 32 * 16) * 4;
    cudaFuncSetAttribute((const void*)conv_bn_kernel<32, 16>,
                         cudaFuncAttributeMaxDynamicSharedMemorySize, smem2);

    dim3 cblk(32, 4);

    // conv1 (3 -> 32), writes g_buf1 [32][768][768]
    conv_bn_kernel<3, 16><<<dim3(24, 48, 2), cblk, smem1>>>(
        image, c1w, c1b, bn1g, bn1b, bn1m, bn1v,
        p_buf1, WW, HH * WW, 0);

    // conv2 (32 -> 64), writes interior of g_integ at [c][y+1][x+1] (stride RS)
    conv_bn_kernel<32, 16><<<dim3(24, 48, 4), cblk, smem2>>>(
        p_buf1, c2w, c2b, bn2g, bn2b, bn2m, bn2v,
        p_integ, RS, IW * RS, RS + 1);

    // integral image: vertical (float4, chunked MLP), then horizontal (register scan)
    vscan_kernel<<<dim3(4, C2N), 64>>>();
    hscan_kernel<<<(C2N * HH) / 8, 256>>>();

    // ROI pooling -> g_flat
    pool_kernel<<<NB, 256>>>(boxes);

    // fc1 -> g_h1 (relu)
    fc1_kernel<<<NB / 4, 128>>>(fc1w, fc1b);

    // fc2 -> out
    fc2_kernel<<<(NB * NCLS + 255) / 256, 256>>>(fc2w, fc2b, out);
}

// round 7
// speedup vs baseline: 1.0859x; 1.0859x over previous
#include <cuda_runtime.h>

#define HH 768
#define WW 768
#define NB 512
#define C1N 32
#define C2N 64
#define IW 769            // logical integral image height/width (H+1)
#define RS 772            // padded integral row stride (16B aligned)
#define CS 768            // conv2 output row stride (compact, aligned)
#define FEAT 1600         // C2 * 5 * 5
#define FC1N 128
#define NCLS 4
#define NSEG 8            // vertical scan segments (768/96)
#define SEGH 96

// ---------------- scratch (no allocations allowed) ----------------
__device__ float g_buf1[C1N * HH * WW];        // conv1 output (32,768,768)
__device__ float g_conv2[C2N * HH * CS];       // conv2 output (64,768,768) aligned
__device__ float g_integ[C2N * IW * RS];       // integral image (64,769,772)
__device__ float g_segsum[C2N * NSEG * CS];    // per-segment column sums
__device__ float g_flat[NB * FEAT];            // pooled features (512,1600)
__device__ float g_h1[NB * FC1N];              // fc1 output (512,128)

// ---------------- packed f32x2 helpers ----------------
typedef unsigned long long ull;

__device__ __forceinline__ ull ffma2(ull a, ull b, ull c) {
    ull d;
    asm("fma.rn.f32x2 %0, %1, %2, %3;" : "=l"(d) : "l"(a), "l"(b), "l"(c));
    return d;
}
__device__ __forceinline__ ull pack2(float lo, float hi) {
    ull r;
    asm("mov.b64 %0, {%1, %2};" : "=l"(r) : "f"(lo), "f"(hi));
    return r;
}
__device__ __forceinline__ void unpack2(ull v, float& lo, float& hi) {
    asm("mov.b64 {%0, %1}, %2;" : "=f"(lo), "=f"(hi) : "l"(v));
}

// ---------------- fused conv3x3 + bias + relu + bn ----------------
// Block: 32x4 threads. Tile: 32 wide x 16 tall. Each thread: 4 rows x OCC out-channels.
// Accumulators packed in f32x2 pairs along the OC dimension (FFMA2 = 2 MACs/slot).
template <int IC, int OCC>
__global__ __launch_bounds__(128)
void conv_bn_kernel(const float* __restrict__ in,
                    const float* __restrict__ wgt,   // [OC][IC][3][3]
                    const float* __restrict__ bias,
                    const float* __restrict__ bng,
                    const float* __restrict__ bnb,
                    const float* __restrict__ bnm,
                    const float* __restrict__ bnv,
                    float* __restrict__ out)
{
    extern __shared__ float smem[];
    float* s_in = smem;                 // [IC][18][34]
    float* s_w  = smem + IC * 18 * 34;  // [9][IC][OCC]  (oc consecutive -> LDS.64 pairs)

    const int tx = threadIdx.x, ty = threadIdx.y;
    const int tid = ty * 32 + tx;
    const int bx0 = blockIdx.x * 32;
    const int by0 = blockIdx.y * 16;
    const int ocBase = blockIdx.z * OCC;

    for (int idx = tid; idx < IC * 18 * 34; idx += 128) {
        int ic = idx / (18 * 34);
        int r  = idx % (18 * 34);
        int yy = r / 34, xx = r % 34;
        int gy = by0 + yy - 1, gx = bx0 + xx - 1;
        float v = 0.f;
        if (gy >= 0 && gy < HH && gx >= 0 && gx < WW)
            v = in[(ic * HH + gy) * WW + gx];
        s_in[idx] = v;
    }
    for (int idx = tid; idx < 9 * IC * OCC; idx += 128) {
        int tap = idx / (IC * OCC);
        int r   = idx % (IC * OCC);
        int ic  = r / OCC, oc = r % OCC;
        s_w[idx] = wgt[((ocBase + oc) * IC + ic) * 9 + tap];
    }
    __syncthreads();

    constexpr int OCP = OCC / 2;
    ull acc[OCP][4];
#pragma unroll
    for (int op = 0; op < OCP; ++op)
#pragma unroll
        for (int p = 0; p < 4; ++p) acc[op][p] = 0ull;

#pragma unroll 1
    for (int ic = 0; ic < IC; ++ic) {
#pragma unroll
        for (int tap = 0; tap < 9; ++tap) {
            const int ky = tap / 3, kx = tap % 3;
            ull vv[4];
#pragma unroll
            for (int p = 0; p < 4; ++p) {
                float v = s_in[(ic * 18 + (ty * 4 + p + ky)) * 34 + tx + kx];
                vv[p] = pack2(v, v);
            }
            const ull* wrow = (const ull*)&s_w[(tap * IC + ic) * OCC];
#pragma unroll
            for (int op = 0; op < OCP; ++op) {
                const ull w2 = wrow[op];
#pragma unroll
                for (int p = 0; p < 4; ++p)
                    acc[op][p] = ffma2(vv[p], w2, acc[op][p]);
            }
        }
    }

#pragma unroll
    for (int op = 0; op < OCP; ++op) {
#pragma unroll
        for (int half = 0; half < 2; ++half) {
            const int ocg = ocBase + op * 2 + half;
            const float b  = bias[ocg];
            const float sc = bng[ocg] / sqrtf(bnv[ocg] + 1e-5f);
            const float sh = bnb[ocg] - bnm[ocg] * sc;
#pragma unroll
            for (int p = 0; p < 4; ++p) {
                float lo, hi;
                unpack2(acc[op][p], lo, hi);
                float vv = (half ? hi : lo) + b;
                vv = vv > 0.f ? vv : 0.f;
                vv = vv * sc + sh;
                const int gy = by0 + ty * 4 + p;
                const int gx = bx0 + tx;
                out[((size_t)ocg * HH + gy) * CS + gx] = vv;
            }
        }
    }
}

// ---------------- integral image: vertical (two-pass segmented) ----------------
// Pass A: each thread sums SEGH rows of its 4 columns -> segment sums.
// 64ch x 8seg x 192thr = 98k threads, fully parallel, BW-bound.
__global__ __launch_bounds__(192)
void vscanA_kernel()
{
    const int tx = threadIdx.x;          // 0..191, columns 4*tx..4*tx+3
    const int seg = blockIdx.x;          // 0..7
    const int c = blockIdx.y;
    const float* src = g_conv2 + (size_t)c * HH * CS + tx * 4;
    const int y0 = seg * SEGH;

    float4 s = make_float4(0.f, 0.f, 0.f, 0.f);
#pragma unroll 1
    for (int ch = 0; ch < SEGH / 8; ++ch) {
        float4 v[8];
#pragma unroll
        for (int r = 0; r < 8; ++r)
            v[r] = *(const float4*)(src + (size_t)(y0 + ch * 8 + r) * CS);
#pragma unroll
        for (int r = 0; r < 8; ++r) {
            s.x += v[r].x; s.y += v[r].y; s.z += v[r].z; s.w += v[r].w;
        }
    }
    *(float4*)(g_segsum + ((size_t)c * NSEG + seg) * CS + tx * 4) = s;

    // zero top row of the integral image (row 0, cols 0..768)
    if (seg == 0) {
        *(float4*)(g_integ + (size_t)c * IW * RS + tx * 4) =
            make_float4(0.f, 0.f, 0.f, 0.f);
        if (tx == 0) g_integ[(size_t)c * IW * RS + 768] = 0.f;
    }
}

// Pass B: prefix the segment sums, then serial scan within the segment,
// writing integ[c][y+1][x] (columns NOT shifted -> aligned float4 stores).
__global__ __launch_bounds__(192)
void vscanB_kernel()
{
    const int tx = threadIdx.x;
    const int seg = blockIdx.x;
    const int c = blockIdx.y;
    const float* src = g_conv2 + (size_t)c * HH * CS + tx * 4;
    float* dst = g_integ + (size_t)c * IW * RS + tx * 4;
    const int y0 = seg * SEGH;

    float4 run = make_float4(0.f, 0.f, 0.f, 0.f);
    for (int s = 0; s < seg; ++s) {
        float4 sv = *(const float4*)(g_segsum + ((size_t)c * NSEG + s) * CS + tx * 4);
        run.x += sv.x; run.y += sv.y; run.z += sv.z; run.w += sv.w;
    }

#pragma unroll 1
    for (int ch = 0; ch < SEGH / 8; ++ch) {
        float4 v[8];
#pragma unroll
        for (int r = 0; r < 8; ++r)
            v[r] = *(const float4*)(src + (size_t)(y0 + ch * 8 + r) * CS);
#pragma unroll
        for (int r = 0; r < 8; ++r) {
            run.x += v[r].x; run.y += v[r].y; run.z += v[r].z; run.w += v[r].w;
            *(float4*)(dst + (size_t)(1 + y0 + ch * 8 + r) * RS) = run;
        }
    }
}

// ---------------- integral image: horizontal ----------------
// Warp per row. Read cols 0..767 (aligned), shuffle-scan in registers,
// write cols 1..768 (the +1 integral shift), col 0 <- 0.
__global__ __launch_bounds__(256)
void hscan_kernel()
{
    const int warp = (blockIdx.x * blockDim.x + threadIdx.x) >> 5;
    const int lane = threadIdx.x & 31;
    if (warp >= C2N * HH) return;
    const int c = warp / HH;
    const int y = warp % HH + 1;
    float* row = g_integ + ((size_t)c * IW + y) * RS;

    float v[24];
#pragma unroll
    for (int k = 0; k < 24; ++k)
        v[k] = row[k * 32 + lane];

    float carry = 0.f;
#pragma unroll
    for (int k = 0; k < 24; ++k) {
#pragma unroll
        for (int d = 1; d < 32; d <<= 1) {
            float n = __shfl_up_sync(0xFFFFFFFFu, v[k], d);
            if (lane >= d) v[k] += n;
        }
        v[k] += carry;
        carry = __shfl_sync(0xFFFFFFFFu, v[k], 31);
    }

#pragma unroll
    for (int k = 0; k < 24; ++k)
        row[1 + k * 32 + lane] = v[k];
    if (lane == 0) row[0] = 0.f;
}

// ---------------- ROI 5x5 pooling via integral image ----------------
__global__ void pool_kernel(const int* __restrict__ boxes)
{
    const int n = blockIdx.x;
    __shared__ int sy0[5], sy1[5], sx0[5], sx1[5];
    const int tid = threadIdx.x;
    if (tid < 5) {
        const int xmin = boxes[n * 4 + 0];
        const int ymin = boxes[n * 4 + 1];
        const int xmax = boxes[n * 4 + 2];
        const int ymax = boxes[n * 4 + 3];
        const int bh = ymax - ymin;
        const int bw = xmax - xmin;
        sy0[tid] = ymin + tid * bh / 5;
        sy1[tid] = ymin + ((tid + 1) * bh + 4) / 5;
        sx0[tid] = xmin + tid * bw / 5;
        sx1[tid] = xmin + ((tid + 1) * bw + 4) / 5;
    }
    __syncthreads();
    for (int e = tid; e < FEAT; e += blockDim.x) {
        const int c = e / 25, ij = e % 25, i = ij / 5, j = ij % 5;
        const float* I = g_integ + (size_t)c * IW * RS;
        const int y0 = sy0[i], y1 = sy1[i], x0 = sx0[j], x1 = sx1[j];
        const float s = I[(size_t)y1 * RS + x1] - I[(size_t)y0 * RS + x1]
                      - I[(size_t)y1 * RS + x0] + I[(size_t)y0 * RS + x0];
        const float area = (float)((y1 - y0) * (x1 - x0));
        g_flat[(size_t)n * FEAT + e] = s / area;
    }
}

// ---------------- fc1: (512,1600) @ (1600,128)^T + relu ----------------
__global__ __launch_bounds__(128)
void fc1_kernel(const float* __restrict__ w, const float* __restrict__ b)
{
    __shared__ float sf[4][FEAT];
    const int nb0 = blockIdx.x * 4;
    const int tid = threadIdx.x;
    for (int i = tid; i < 4 * FEAT; i += 128)
        sf[i / FEAT][i % FEAT] = g_flat[(size_t)(nb0 + i / FEAT) * FEAT + i % FEAT];
    __syncthreads();

    float acc0 = 0.f, acc1 = 0.f, acc2 = 0.f, acc3 = 0.f;
    const float* wr = w + (size_t)tid * FEAT;
    for (int k = 0; k < FEAT; k += 4) {
        const float4 wv = *(const float4*)(wr + k);
        acc0 += sf[0][k] * wv.x + sf[0][k + 1] * wv.y + sf[0][k + 2] * wv.z + sf[0][k + 3] * wv.w;
        acc1 += sf[1][k] * wv.x + sf[1][k + 1] * wv.y + sf[1][k + 2] * wv.z + sf[1][k + 3] * wv.w;
        acc2 += sf[2][k] * wv.x + sf[2][k + 1] * wv.y + sf[2][k + 2] * wv.z + sf[2][k + 3] * wv.w;
        acc3 += sf[3][k] * wv.x + sf[3][k + 1] * wv.y + sf[3][k + 2] * wv.z + sf[3][k + 3] * wv.w;
    }
    const float bb = b[tid];
    float r0 = acc0 + bb, r1 = acc1 + bb, r2 = acc2 + bb, r3 = acc3 + bb;
    g_h1[(size_t)(nb0 + 0) * FC1N + tid] = r0 > 0.f ? r0 : 0.f;
    g_h1[(size_t)(nb0 + 1) * FC1N + tid] = r1 > 0.f ? r1 : 0.f;
    g_h1[(size_t)(nb0 + 2) * FC1N + tid] = r2 > 0.f ? r2 : 0.f;
    g_h1[(size_t)(nb0 + 3) * FC1N + tid] = r3 > 0.f ? r3 : 0.f;
}

// ---------------- fc2: (512,128) @ (128,4)^T ----------------
__global__ void fc2_kernel(const float* __restrict__ w, const float* __restrict__ bias,
                           float* __restrict__ out)
{
    const int t = blockIdx.x * blockDim.x + threadIdx.x;
    if (t >= NB * NCLS) return;
    const int n = t / NCLS, o = t % NCLS;
    const float* h  = g_h1 + (size_t)n * FC1N;
    const float* wr = w + (size_t)o * FC1N;
    float acc = 0.f;
#pragma unroll 8
    for (int k = 0; k < FC1N; ++k) acc += h[k] * wr[k];
    out[t] = acc + bias[o];
}

// ---------------- launch ----------------
extern "C" void kernel_launch(void* const* d_in, const int* in_sizes, int n_in,
                              void* d_out, int out_size)
{
    const float* image  = (const float*)d_in[0];
    const int*   boxes  = (const int*)d_in[1];
    const float* c1w    = (const float*)d_in[2];
    const float* c1b    = (const float*)d_in[3];
    const float* bn1g   = (const float*)d_in[4];
    const float* bn1b   = (const float*)d_in[5];
    const float* bn1m   = (const float*)d_in[6];
    const float* bn1v   = (const float*)d_in[7];
    const float* c2w    = (const float*)d_in[8];
    const float* c2b    = (const float*)d_in[9];
    const float* bn2g   = (const float*)d_in[10];
    const float* bn2b   = (const float*)d_in[11];
    const float* bn2m   = (const float*)d_in[12];
    const float* bn2v   = (const float*)d_in[13];
    const float* fc1w   = (const float*)d_in[14];
    const float* fc1b   = (const float*)d_in[15];
    const float* fc2w   = (const float*)d_in[16];
    const float* fc2b   = (const float*)d_in[17];
    float* out = (float*)d_out;

    float *p_buf1, *p_conv2;
    cudaGetSymbolAddress((void**)&p_buf1, g_buf1);
    cudaGetSymbolAddress((void**)&p_conv2, g_conv2);

    const int smem1 = (3 * 18 * 34 + 9 * 3 * 16) * 4;
    const int smem2 = (32 * 18 * 34 + 9 * 32 * 16) * 4;
    cudaFuncSetAttribute((const void*)conv_bn_kernel<32, 16>,
                         cudaFuncAttributeMaxDynamicSharedMemorySize, smem2);

    dim3 cblk(32, 4);

    // conv1 (3 -> 32), writes g_buf1 [32][768][768]  (note: CS == WW == 768)
    conv_bn_kernel<3, 16><<<dim3(24, 48, 2), cblk, smem1>>>(
        image, c1w, c1b, bn1g, bn1b, bn1m, bn1v, p_buf1);

    // conv2 (32 -> 64), writes compact aligned g_conv2 [64][768][768]
    conv_bn_kernel<32, 16><<<dim3(24, 48, 4), cblk, smem2>>>(
        p_buf1, c2w, c2b, bn2g, bn2b, bn2m, bn2v, p_conv2);

    // vertical cumsum: segmented two-pass (parallel, BW-bound)
    vscanA_kernel<<<dim3(NSEG, C2N), 192>>>();
    vscanB_kernel<<<dim3(NSEG, C2N), 192>>>();

    // horizontal cumsum (+1 column shift into final integral layout)
    hscan_kernel<<<(C2N * HH) / 8, 256>>>();

    // ROI pooling -> g_flat
    pool_kernel<<<NB, 256>>>(boxes);

    // fc1 -> g_h1 (relu)
    fc1_kernel<<<NB / 4, 128>>>(fc1w, fc1b);

    // fc2 -> out
    fc2_kernel<<<(NB * NCLS + 255) / 256, 256>>>(fc2w, fc2b, out);
}

// round 10
// speedup vs baseline: 1.2973x; 1.1946x over previous
#include <cuda_runtime.h>

#define HH 768
#define WW 768
#define NB 512
#define C1N 32
#define C2N 64
#define IW 769            // logical integral image height/width (H+1)
#define RS 772            // padded integral row stride (16B aligned)
#define CS 768            // conv2 output row stride (compact, aligned)
#define FEAT 1600         // C2 * 5 * 5
#define FC1N 128
#define NCLS 4
#define NSEG 8            // vertical scan segments (768/96)
#define SEGH 96

// ---------------- scratch (no allocations allowed) ----------------
__device__ float g_buf1[C1N * HH * WW];        // conv1 output (32,768,768)
__device__ float g_conv2[C2N * HH * CS];       // conv2 output (64,768,768) aligned
__device__ float g_integ[C2N * IW * RS];       // integral image (64,769,772)
__device__ float g_segsum[C2N * NSEG * CS];    // per-segment column sums
__device__ float g_flat[NB * FEAT];            // pooled features (512,1600)
__device__ float g_h1[NB * FC1N];              // fc1 output (512,128)

// ---------------- packed f32x2 helpers ----------------
typedef unsigned long long ull;

__device__ __forceinline__ ull ffma2(ull a, ull b, ull c) {
    ull d;
    asm("fma.rn.f32x2 %0, %1, %2, %3;" : "=l"(d) : "l"(a), "l"(b), "l"(c));
    return d;
}
__device__ __forceinline__ ull pack2(float lo, float hi) {
    ull r;
    asm("mov.b64 %0, {%1, %2};" : "=l"(r) : "f"(lo), "f"(hi));
    return r;
}
__device__ __forceinline__ void unpack2(ull v, float& lo, float& hi) {
    asm("mov.b64 {%0, %1}, %2;" : "=f"(lo), "=f"(hi) : "l"(v));
}

// ---------------- profiling-slot dummy ----------------
__global__ void dummy_kernel() {}

// ---------------- fused conv3x3 + bias + relu + bn ----------------
// Block: 32x4 threads. Tile: 32 wide x 16 tall. Each thread: 4 rows x OCC out-channels.
// IC processed in chunks of ICC (smem halved -> 4 CTAs/SM for conv2).
// Per-ic 6x3 input window kept in registers across all 9 taps.
// Accumulation order identical to previous rounds (ic outer, tap inner).
template <int IC, int ICC, int OCC>
__global__ __launch_bounds__(128)
void conv_bn_kernel(const float* __restrict__ in,
                    const float* __restrict__ wgt,   // [OC][IC][3][3]
                    const float* __restrict__ bias,
                    const float* __restrict__ bng,
                    const float* __restrict__ bnb,
                    const float* __restrict__ bnm,
                    const float* __restrict__ bnv,
                    float* __restrict__ out)
{
    extern __shared__ float smem[];
    float* s_in = smem;                  // [ICC][18][34]
    float* s_w  = smem + ICC * 18 * 34;  // [9][ICC][OCC] (oc consecutive -> LDS.64)

    const int tx = threadIdx.x, ty = threadIdx.y;
    const int tid = ty * 32 + tx;
    const int bx0 = blockIdx.x * 32;
    const int by0 = blockIdx.y * 16;
    const int ocBase = blockIdx.z * OCC;

    constexpr int OCP = OCC / 2;
    ull acc[OCP][4];
#pragma unroll
    for (int op = 0; op < OCP; ++op)
#pragma unroll
        for (int p = 0; p < 4; ++p) acc[op][p] = 0ull;

#pragma unroll 1
    for (int chk = 0; chk < IC / ICC; ++chk) {
        if (chk > 0) __syncthreads();   // protect smem reuse

        // load input chunk (with zero padding at image borders)
        for (int idx = tid; idx < ICC * 18 * 34; idx += 128) {
            int ic = idx / (18 * 34);
            int r  = idx % (18 * 34);
            int yy = r / 34, xx = r % 34;
            int gy = by0 + yy - 1, gx = bx0 + xx - 1;
            float v = 0.f;
            if (gy >= 0 && gy < HH && gx >= 0 && gx < WW)
                v = in[((size_t)(chk * ICC + ic) * HH + gy) * WW + gx];
            s_in[idx] = v;
        }
        // load weight chunk transposed to [tap][ic][oc]
        for (int idx = tid; idx < 9 * ICC * OCC; idx += 128) {
            int tap = idx / (ICC * OCC);
            int r   = idx % (ICC * OCC);
            int ic  = r / OCC, oc = r % OCC;
            s_w[idx] = wgt[((ocBase + oc) * IC + chk * ICC + ic) * 9 + tap];
        }
        __syncthreads();

#pragma unroll 1
        for (int ic = 0; ic < ICC; ++ic) {
            // 6 rows x 3 cols register window for this thread's 4 output rows
            float v[6][3];
#pragma unroll
            for (int r = 0; r < 6; ++r)
#pragma unroll
                for (int q = 0; q < 3; ++q)
                    v[r][q] = s_in[(ic * 18 + ty * 4 + r) * 34 + tx + q];

#pragma unroll
            for (int tap = 0; tap < 9; ++tap) {
                const int ky = tap / 3, kx = tap % 3;
                ull vv[4];
#pragma unroll
                for (int p = 0; p < 4; ++p)
                    vv[p] = pack2(v[p + ky][kx], v[p + ky][kx]);
                const ull* wrow = (const ull*)&s_w[(tap * ICC + ic) * OCC];
#pragma unroll
                for (int op = 0; op < OCP; ++op) {
                    const ull w2 = wrow[op];
#pragma unroll
                    for (int p = 0; p < 4; ++p)
                        acc[op][p] = ffma2(vv[p], w2, acc[op][p]);
                }
            }
        }
    }

#pragma unroll
    for (int op = 0; op < OCP; ++op) {
#pragma unroll
        for (int half = 0; half < 2; ++half) {
            const int ocg = ocBase + op * 2 + half;
            const float b  = bias[ocg];
            const float sc = bng[ocg] / sqrtf(bnv[ocg] + 1e-5f);
            const float sh = bnb[ocg] - bnm[ocg] * sc;
#pragma unroll
            for (int p = 0; p < 4; ++p) {
                float lo, hi;
                unpack2(acc[op][p], lo, hi);
                float vv = (half ? hi : lo) + b;
                vv = vv > 0.f ? vv : 0.f;
                vv = vv * sc + sh;
                const int gy = by0 + ty * 4 + p;
                const int gx = bx0 + tx;
                out[((size_t)ocg * HH + gy) * CS + gx] = vv;
            }
        }
    }
}

// ---------------- integral image: vertical (two-pass segmented) ----------------
__global__ __launch_bounds__(192)
void vscanA_kernel()
{
    const int tx = threadIdx.x;          // 0..191, columns 4*tx..4*tx+3
    const int seg = blockIdx.x;          // 0..7
    const int c = blockIdx.y;
    const float* src = g_conv2 + (size_t)c * HH * CS + tx * 4;
    const int y0 = seg * SEGH;

    float4 s = make_float4(0.f, 0.f, 0.f, 0.f);
#pragma unroll 1
    for (int ch = 0; ch < SEGH / 8; ++ch) {
        float4 v[8];
#pragma unroll
        for (int r = 0; r < 8; ++r)
            v[r] = *(const float4*)(src + (size_t)(y0 + ch * 8 + r) * CS);
#pragma unroll
        for (int r = 0; r < 8; ++r) {
            s.x += v[r].x; s.y += v[r].y; s.z += v[r].z; s.w += v[r].w;
        }
    }
    *(float4*)(g_segsum + ((size_t)c * NSEG + seg) * CS + tx * 4) = s;

    // zero top row of the integral image (row 0, cols 0..768)
    if (seg == 0) {
        *(float4*)(g_integ + (size_t)c * IW * RS + tx * 4) =
            make_float4(0.f, 0.f, 0.f, 0.f);
        if (tx == 0) g_integ[(size_t)c * IW * RS + 768] = 0.f;
    }
}

__global__ __launch_bounds__(192)
void vscanB_kernel()
{
    const int tx = threadIdx.x;
    const int seg = blockIdx.x;
    const int c = blockIdx.y;
    const float* src = g_conv2 + (size_t)c * HH * CS + tx * 4;
    float* dst = g_integ + (size_t)c * IW * RS + tx * 4;
    const int y0 = seg * SEGH;

    float4 run = make_float4(0.f, 0.f, 0.f, 0.f);
    for (int s = 0; s < seg; ++s) {
        float4 sv = *(const float4*)(g_segsum + ((size_t)c * NSEG + s) * CS + tx * 4);
        run.x += sv.x; run.y += sv.y; run.z += sv.z; run.w += sv.w;
    }

#pragma unroll 1
    for (int ch = 0; ch < SEGH / 8; ++ch) {
        float4 v[8];
#pragma unroll
        for (int r = 0; r < 8; ++r)
            v[r] = *(const float4*)(src + (size_t)(y0 + ch * 8 + r) * CS);
#pragma unroll
        for (int r = 0; r < 8; ++r) {
            run.x += v[r].x; run.y += v[r].y; run.z += v[r].z; run.w += v[r].w;
            *(float4*)(dst + (size_t)(1 + y0 + ch * 8 + r) * RS) = run;
        }
    }
}

// ---------------- integral image: horizontal ----------------
__global__ __launch_bounds__(256)
void hscan_kernel()
{
    const int warp = (blockIdx.x * blockDim.x + threadIdx.x) >> 5;
    const int lane = threadIdx.x & 31;
    if (warp >= C2N * HH) return;
    const int c = warp / HH;
    const int y = warp % HH + 1;
    float* row = g_integ + ((size_t)c * IW + y) * RS;

    float v[24];
#pragma unroll
    for (int k = 0; k < 24; ++k)
        v[k] = row[k * 32 + lane];

    float carry = 0.f;
#pragma unroll
    for (int k = 0; k < 24; ++k) {
#pragma unroll
        for (int d = 1; d < 32; d <<= 1) {
            float n = __shfl_up_sync(0xFFFFFFFFu, v[k], d);
            if (lane >= d) v[k] += n;
        }
        v[k] += carry;
        carry = __shfl_sync(0xFFFFFFFFu, v[k], 31);
    }

#pragma unroll
    for (int k = 0; k < 24; ++k)
        row[1 + k * 32 + lane] = v[k];
    if (lane == 0) row[0] = 0.f;
}

// ---------------- ROI 5x5 pooling via integral image ----------------
__global__ void pool_kernel(const int* __restrict__ boxes)
{
    const int n = blockIdx.x;
    __shared__ int sy0[5], sy1[5], sx0[5], sx1[5];
    const int tid = threadIdx.x;
    if (tid < 5) {
        const int xmin = boxes[n * 4 + 0];
        const int ymin = boxes[n * 4 + 1];
        const int xmax = boxes[n * 4 + 2];
        const int ymax = boxes[n * 4 + 3];
        const int bh = ymax - ymin;
        const int bw = xmax - xmin;
        sy0[tid] = ymin + tid * bh / 5;
        sy1[tid] = ymin + ((tid + 1) * bh + 4) / 5;
        sx0[tid] = xmin + tid * bw / 5;
        sx1[tid] = xmin + ((tid + 1) * bw + 4) / 5;
    }
    __syncthreads();
    for (int e = tid; e < FEAT; e += blockDim.x) {
        const int c = e / 25, ij = e % 25, i = ij / 5, j = ij % 5;
        const float* I = g_integ + (size_t)c * IW * RS;
        const int y0 = sy0[i], y1 = sy1[i], x0 = sx0[j], x1 = sx1[j];
        const float s = I[(size_t)y1 * RS + x1] - I[(size_t)y0 * RS + x1]
                      - I[(size_t)y1 * RS + x0] + I[(size_t)y0 * RS + x0];
        const float area = (float)((y1 - y0) * (x1 - x0));
        g_flat[(size_t)n * FEAT + e] = s / area;
    }
}

// ---------------- fc1: (512,1600) @ (1600,128)^T + relu ----------------
__global__ __launch_bounds__(128)
void fc1_kernel(const float* __restrict__ w, const float* __restrict__ b)
{
    __shared__ float sf[4][FEAT];
    const int nb0 = blockIdx.x * 4;
    const int tid = threadIdx.x;
    for (int i = tid; i < 4 * FEAT; i += 128)
        sf[i / FEAT][i % FEAT] = g_flat[(size_t)(nb0 + i / FEAT) * FEAT + i % FEAT];
    __syncthreads();

    float acc0 = 0.f, acc1 = 0.f, acc2 = 0.f, acc3 = 0.f;
    const float* wr = w + (size_t)tid * FEAT;
    for (int k = 0; k < FEAT; k += 4) {
        const float4 wv = *(const float4*)(wr + k);
        acc0 += sf[0][k] * wv.x + sf[0][k + 1] * wv.y + sf[0][k + 2] * wv.z + sf[0][k + 3] * wv.w;
        acc1 += sf[1][k] * wv.x + sf[1][k + 1] * wv.y + sf[1][k + 2] * wv.z + sf[1][k + 3] * wv.w;
        acc2 += sf[2][k] * wv.x + sf[2][k + 1] * wv.y + sf[2][k + 2] * wv.z + sf[2][k + 3] * wv.w;
        acc3 += sf[3][k] * wv.x + sf[3][k + 1] * wv.y + sf[3][k + 2] * wv.z + sf[3][k + 3] * wv.w;
    }
    const float bb = b[tid];
    float r0 = acc0 + bb, r1 = acc1 + bb, r2 = acc2 + bb, r3 = acc3 + bb;
    g_h1[(size_t)(nb0 + 0) * FC1N + tid] = r0 > 0.f ? r0 : 0.f;
    g_h1[(size_t)(nb0 + 1) * FC1N + tid] = r1 > 0.f ? r1 : 0.f;
    g_h1[(size_t)(nb0 + 2) * FC1N + tid] = r2 > 0.f ? r2 : 0.f;
    g_h1[(size_t)(nb0 + 3) * FC1N + tid] = r3 > 0.f ? r3 : 0.f;
}

// ---------------- fc2: (512,128) @ (128,4)^T ----------------
__global__ void fc2_kernel(const float* __restrict__ w, const float* __restrict__ bias,
                           float* __restrict__ out)
{
    const int t = blockIdx.x * blockDim.x + threadIdx.x;
    if (t >= NB * NCLS) return;
    const int n = t / NCLS, o = t % NCLS;
    const float* h  = g_h1 + (size_t)n * FC1N;
    const float* wr = w + (size_t)o * FC1N;
    float acc = 0.f;
#pragma unroll 8
    for (int k = 0; k < FC1N; ++k) acc += h[k] * wr[k];
    out[t] = acc + bias[o];
}

// ---------------- launch ----------------
extern "C" void kernel_launch(void* const* d_in, const int* in_sizes, int n_in,
                              void* d_out, int out_size)
{
    const float* image  = (const float*)d_in[0];
    const int*   boxes  = (const int*)d_in[1];
    const float* c1w    = (const float*)d_in[2];
    const float* c1b    = (const float*)d_in[3];
    const float* bn1g   = (const float*)d_in[4];
    const float* bn1b   = (const float*)d_in[5];
    const float* bn1m   = (const float*)d_in[6];
    const float* bn1v   = (const float*)d_in[7];
    const float* c2w    = (const float*)d_in[8];
    const float* c2b    = (const float*)d_in[9];
    const float* bn2g   = (const float*)d_in[10];
    const float* bn2b   = (const float*)d_in[11];
    const float* bn2m   = (const float*)d_in[12];
    const float* bn2v   = (const float*)d_in[13];
    const float* fc1w   = (const float*)d_in[14];
    const float* fc1b   = (const float*)d_in[15];
    const float* fc2w   = (const float*)d_in[16];
    const float* fc2b   = (const float*)d_in[17];
    float* out = (float*)d_out;

    float *p_buf1, *p_conv2;
    cudaGetSymbolAddress((void**)&p_buf1, g_buf1);
    cudaGetSymbolAddress((void**)&p_conv2, g_conv2);

    const int smem1 = (3 * 18 * 34 + 9 * 3 * 16) * 4;
    const int smem2 = (16 * 18 * 34 + 9 * 16 * 16) * 4;
    cudaFuncSetAttribute((const void*)conv_bn_kernel<32, 16, 16>,
                         cudaFuncAttributeMaxDynamicSharedMemorySize, smem2);

    dim3 cblk(32, 4);

    // slots 1-2: dummies so ncu's fixed capture slot (4th launch) lands on conv2
    dummy_kernel<<<1, 32>>>();
    dummy_kernel<<<1, 32>>>();

    // slot 3: conv1 (3 -> 32), writes g_buf1 [32][768][768]
    conv_bn_kernel<3, 3, 16><<<dim3(24, 48, 2), cblk, smem1>>>(
        image, c1w, c1b, bn1g, bn1b, bn1m, bn1v, p_buf1);

    // slot 4 (PROFILED): conv2 (32 -> 64), writes g_conv2 [64][768][768]
    conv_bn_kernel<32, 16, 16><<<dim3(24, 48, 4), cblk, smem2>>>(
        p_buf1, c2w, c2b, bn2g, bn2b, bn2m, bn2v, p_conv2);

    // vertical cumsum: segmented two-pass (parallel, BW-bound)
    vscanA_kernel<<<dim3(NSEG, C2N), 192>>>();
    vscanB_kernel<<<dim3(NSEG, C2N), 192>>>();

    // horizontal cumsum (+1 column shift into final integral layout)
    hscan_kernel<<<(C2N * HH) / 8, 256>>>();

    // ROI pooling -> g_flat
    pool_kernel<<<NB, 256>>>(boxes);

    // fc1 -> g_h1 (relu)
    fc1_kernel<<<NB / 4, 128>>>(fc1w, fc1b);

    // fc2 -> out
    fc2_kernel<<<(NB * NCLS + 255) / 256, 256>>>(fc2w, fc2b, out);
}

// round 15
// speedup vs baseline: 1.8980x; 1.4631x over previous
#include <cuda_runtime.h>
#include <cuda_fp16.h>
#include <cstdint>

#define HH 768
#define WW 768
#define NB 512
#define C1N 32
#define C2N 64
#define IW 769            // logical integral image height/width (H+1)
#define RS 772            // padded integral row stride (16B aligned)
#define CS 768            // conv2 output row stride (compact, aligned)
#define FEAT 1600         // C2 * 5 * 5
#define FC1N 128
#define NCLS 4
#define NSEG 8            // vertical scan segments (768/96)
#define SEGH 96
#define NTILES (HH * 6)   // conv2 tiles: 768 rows x 6 x-tiles of 128 px

// smem layout for conv2 (bytes)
#define SI_HI 0
#define SI_LO 31680
#define SW_HI 63360
#define SW_LO 109440
#define S_OUT 155520
#define S_BN  189312
#define SMEM_CONV2 190080

// ---------------- scratch (no allocations allowed) ----------------
__device__ __half g_act_hi[HH * WW * C1N];   // conv1 out hi, [y][x][ic]
__device__ __half g_act_lo[HH * WW * C1N];   // conv1 out lo, [y][x][ic]
__device__ float g_conv2[C2N * HH * CS];     // conv2 output (64,768,768)
__device__ float g_integ[C2N * IW * RS];     // integral image (64,769,772)
__device__ float g_segsum[C2N * NSEG * CS];  // per-segment column sums
__device__ float g_flat[NB * FEAT];          // pooled features (512,1600)
__device__ float g_h1[NB * FC1N];            // fc1 output (512,128)

// ---------------- packed f32x2 helpers ----------------
typedef unsigned long long ull;

__device__ __forceinline__ ull ffma2(ull a, ull b, ull c) {
    ull d;
    asm("fma.rn.f32x2 %0, %1, %2, %3;" : "=l"(d) : "l"(a), "l"(b), "l"(c));
    return d;
}
__device__ __forceinline__ ull pack2(float lo, float hi) {
    ull r;
    asm("mov.b64 %0, {%1, %2};" : "=l"(r) : "f"(lo), "f"(hi));
    return r;
}
__device__ __forceinline__ void unpack2(ull v, float& lo, float& hi) {
    asm("mov.b64 {%0, %1}, %2;" : "=f"(lo), "=f"(hi) : "l"(v));
}

// ---------------- mma.sync / ldmatrix helpers (arch-agnostic PTX) ----------------
__device__ __forceinline__ uint32_t smem_to_u32(const void* p) {
    uint32_t a;
    asm("{ .reg .u64 t; cvta.to.shared.u64 t, %1; cvt.u32.u64 %0, t; }" : "=r"(a) : "l"(p));
    return a;
}
__device__ __forceinline__ void ldsm_x4(uint32_t* r, uint32_t addr) {
    asm volatile("ldmatrix.sync.aligned.m8n8.x4.shared.b16 {%0,%1,%2,%3}, [%4];"
                 : "=r"(r[0]), "=r"(r[1]), "=r"(r[2]), "=r"(r[3]) : "r"(addr));
}
__device__ __forceinline__ void ldsm_x2(uint32_t* r, uint32_t addr) {
    asm volatile("ldmatrix.sync.aligned.m8n8.x2.shared.b16 {%0,%1}, [%2];"
                 : "=r"(r[0]), "=r"(r[1]) : "r"(addr));
}
__device__ __forceinline__ void mma_f16(float* d, const uint32_t* a, const uint32_t* b) {
    asm volatile("mma.sync.aligned.m16n8k16.row.col.f32.f16.f16.f32 "
                 "{%0,%1,%2,%3}, {%4,%5,%6,%7}, {%8,%9}, {%0,%1,%2,%3};"
                 : "+f"(d[0]), "+f"(d[1]), "+f"(d[2]), "+f"(d[3])
                 : "r"(a[0]), "r"(a[1]), "r"(a[2]), "r"(a[3]), "r"(b[0]), "r"(b[1]));
}

// ---------------- profiling-slot dummy ----------------
__global__ void dummy_kernel() {}

// ---------------- conv1: fused conv3x3 + bias + relu + bn -> fp16 hi/lo [y][x][ic]
__global__ __launch_bounds__(128)
void conv1_kernel(const float* __restrict__ in,
                  const float* __restrict__ wgt,   // [32][3][3][3]
                  const float* __restrict__ bias,
                  const float* __restrict__ bng,
                  const float* __restrict__ bnb,
                  const float* __restrict__ bnm,
                  const float* __restrict__ bnv)
{
    constexpr int IC = 3, OCC = 16;
    __shared__ float s_in[IC * 18 * 34];
    __shared__ float s_w[9 * IC * OCC];

    const int tx = threadIdx.x, ty = threadIdx.y;
    const int tid = ty * 32 + tx;
    const int bx0 = blockIdx.x * 32;
    const int by0 = blockIdx.y * 16;
    const int ocBase = blockIdx.z * OCC;

    for (int idx = tid; idx < IC * 18 * 34; idx += 128) {
        int ic = idx / (18 * 34);
        int r  = idx % (18 * 34);
        int yy = r / 34, xx = r % 34;
        int gy = by0 + yy - 1, gx = bx0 + xx - 1;
        float v = 0.f;
        if (gy >= 0 && gy < HH && gx >= 0 && gx < WW)
            v = in[(ic * HH + gy) * WW + gx];
        s_in[idx] = v;
    }
    for (int idx = tid; idx < 9 * IC * OCC; idx += 128) {
        int tap = idx / (IC * OCC);
        int r   = idx % (IC * OCC);
        int ic  = r / OCC, oc = r % OCC;
        s_w[idx] = wgt[((ocBase + oc) * IC + ic) * 9 + tap];
    }
    __syncthreads();

    constexpr int OCP = OCC / 2;
    ull acc[OCP][4];
#pragma unroll
    for (int op = 0; op < OCP; ++op)
#pragma unroll
        for (int p = 0; p < 4; ++p) acc[op][p] = 0ull;

#pragma unroll
    for (int ic = 0; ic < IC; ++ic) {
        float v[6][3];
#pragma unroll
        for (int r = 0; r < 6; ++r)
#pragma unroll
            for (int q = 0; q < 3; ++q)
                v[r][q] = s_in[(ic * 18 + ty * 4 + r) * 34 + tx + q];
#pragma unroll
        for (int tap = 0; tap < 9; ++tap) {
            const int ky = tap / 3, kx = tap % 3;
            ull vv[4];
#pragma unroll
            for (int p = 0; p < 4; ++p)
                vv[p] = pack2(v[p + ky][kx], v[p + ky][kx]);
            const ull* wrow = (const ull*)&s_w[(tap * IC + ic) * OCC];
#pragma unroll
            for (int op = 0; op < OCP; ++op) {
                const ull w2 = wrow[op];
#pragma unroll
                for (int p = 0; p < 4; ++p)
                    acc[op][p] = ffma2(vv[p], w2, acc[op][p]);
            }
        }
    }

    float bb[OCC], scv[OCC], shv[OCC];
#pragma unroll
    for (int j = 0; j < OCC; ++j) {
        const int ocg = ocBase + j;
        bb[j]  = bias[ocg];
        scv[j] = bng[ocg] / sqrtf(bnv[ocg] + 1e-5f);
        shv[j] = bnb[ocg] - bnm[ocg] * scv[j];
    }

#pragma unroll
    for (int p = 0; p < 4; ++p) {
        float res[OCC];
#pragma unroll
        for (int op = 0; op < OCP; ++op) {
            float lo, hi;
            unpack2(acc[op][p], lo, hi);
            res[op * 2 + 0] = lo;
            res[op * 2 + 1] = hi;
        }
        uint32_t hw[8], lw[8];
#pragma unroll
        for (int j = 0; j < OCC; ++j) {
            float vv = res[j] + bb[j];
            vv = vv > 0.f ? vv : 0.f;
            vv = vv * scv[j] + shv[j];
            __half h = __float2half(vv);
            float rem = vv - __half2float(h);
            __half l = __float2half(rem);
            unsigned short hu = __half_as_ushort(h);
            unsigned short lu = __half_as_ushort(l);
            if (j & 1) {
                hw[j >> 1] |= ((uint32_t)hu) << 16;
                lw[j >> 1] |= ((uint32_t)lu) << 16;
            } else {
                hw[j >> 1] = hu;
                lw[j >> 1] = lu;
            }
        }
        const int gy = by0 + ty * 4 + p;
        const int gx = bx0 + tx;
        const size_t pix = (size_t)gy * WW + gx;
        uint4* dh = (uint4*)g_act_hi + pix * 4 + (ocBase >> 3);
        uint4* dl = (uint4*)g_act_lo + pix * 4 + (ocBase >> 3);
        dh[0] = make_uint4(hw[0], hw[1], hw[2], hw[3]);
        dh[1] = make_uint4(hw[4], hw[5], hw[6], hw[7]);
        dl[0] = make_uint4(lw[0], lw[1], lw[2], lw[3]);
        dl[1] = make_uint4(lw[4], lw[5], lw[6], lw[7]);
    }
}

// ---------------- conv2: mma.sync implicit GEMM (fp16 hi/lo split) ----------------
// Persistent 148 CTAs x 128 threads (4 warps). Tile = 128 px of one row x 64 oc.
// Warp = 32 px (2 m-frags). K = 9 taps x 32 ic = 288 -> 18 k16-steps.
// Chains: hi*whi + lo*whi + hi*wlo (xl*wl dropped, <=2^-22).
__global__ __launch_bounds__(128, 1)
void conv2_mma_kernel(const float* __restrict__ wgt,   // [64][32][3][3]
                      const float* __restrict__ bias,
                      const float* __restrict__ bng,
                      const float* __restrict__ bnb,
                      const float* __restrict__ bnm,
                      const float* __restrict__ bnv)
{
    extern __shared__ char smem[];
    const int tid = threadIdx.x;
    const int wid = tid >> 5, lane = tid & 31;
    const uint32_t sb = smem_to_u32(smem);

    float* s_bias = (float*)(smem + S_BN);
    float* s_sc   = s_bias + 64;
    float* s_sh   = s_sc + 64;
    if (tid < 64) {
        float sc = bng[tid] / sqrtf(bnv[tid] + 1e-5f);
        s_bias[tid] = bias[tid];
        s_sc[tid]   = sc;
        s_sh[tid]   = bnb[tid] - bnm[tid] * sc;
    }

    // weights -> smem, [tap][oc] rows of 32 ic halves, 80B stride (conflict-free ldmatrix)
    for (int idx = tid; idx < 9 * 64 * 32; idx += 128) {
        const int t = idx / 2048, r = idx % 2048;
        const int oc = r >> 5, ic = r & 31;
        const float w = wgt[((size_t)(oc * 32 + ic)) * 9 + t];
        const __half h = __float2half(w);
        const __half l = __float2half(w - __half2float(h));
        *(__half*)(smem + SW_HI + (t * 64 + oc) * 80 + ic * 2) = h;
        *(__half*)(smem + SW_LO + (t * 64 + oc) * 80 + ic * 2) = l;
    }
    __syncthreads();

    // lane-constant address components
    const int m16 = lane & 15, kh4 = lane >> 4;
    const uint32_t aHi0 = sb + SI_HI + (uint32_t)(wid * 32 + m16) * 80 + kh4 * 16;
    const uint32_t aHi1 = aHi0 + 16 * 80;
    const uint32_t aLo0 = aHi0 + (SI_LO - SI_HI);
    const uint32_t aLo1 = aHi1 + (SI_LO - SI_HI);
    const int n8 = lane & 7, bh8 = (lane >> 3) & 1;
    const uint32_t bHi = sb + SW_HI + (uint32_t)n8 * 80 + bh8 * 16;
    const uint32_t bLo = bHi + (SW_LO - SW_HI);

    for (int tile = blockIdx.x; tile < NTILES; tile += gridDim.x) {
        const int y = tile / 6, x0 = (tile % 6) * 128;

        // ---- stage input: rows y-1..y+1, x0-1..x0+128 (130 px), hi+lo ----
        for (int i = tid; i < 3 * 130 * 4; i += 128) {
            const int q = i & 3, xl = (i >> 2) % 130, dy = (i >> 2) / 130;
            const int gy = y + dy - 1, gx = x0 - 1 + xl;
            uint4 vh = make_uint4(0u, 0u, 0u, 0u), vl = vh;
            if (gy >= 0 && gy < HH && gx >= 0 && gx < WW) {
                const size_t pix = (size_t)gy * WW + gx;
                vh = ((const uint4*)g_act_hi)[pix * 4 + q];
                vl = ((const uint4*)g_act_lo)[pix * 4 + q];
            }
            *(uint4*)(smem + SI_HI + (dy * 132 + xl) * 80 + q * 16) = vh;
            *(uint4*)(smem + SI_LO + (dy * 132 + xl) * 80 + q * 16) = vl;
        }
        __syncthreads();

        float acc[2][8][4];
#pragma unroll
        for (int mf = 0; mf < 2; ++mf)
#pragma unroll
            for (int nf = 0; nf < 8; ++nf)
#pragma unroll
                for (int e = 0; e < 4; ++e) acc[mf][nf][e] = 0.f;

#pragma unroll 1
        for (int ks = 0; ks < 18; ++ks) {
            const int tap = ks >> 1, ich = ks & 1;
            const int ky = tap / 3, kx = tap % 3;
            const uint32_t ao = (uint32_t)(ky * 132 + kx) * 80 + ich * 32;
            uint32_t ah0[4], ah1[4], al0[4], al1[4];
            ldsm_x4(ah0, aHi0 + ao);
            ldsm_x4(ah1, aHi1 + ao);
            ldsm_x4(al0, aLo0 + ao);
            ldsm_x4(al1, aLo1 + ao);
            const uint32_t bo = (uint32_t)(tap * 64) * 80 + ich * 32;
#pragma unroll
            for (int nf = 0; nf < 8; ++nf) {
                uint32_t bh[2], bl[2];
                ldsm_x2(bh, bHi + bo + nf * 8 * 80);
                ldsm_x2(bl, bLo + bo + nf * 8 * 80);
                mma_f16(acc[0][nf], ah0, bh);
                mma_f16(acc[1][nf], ah1, bh);
                mma_f16(acc[0][nf], al0, bh);
                mma_f16(acc[1][nf], al1, bh);
                mma_f16(acc[0][nf], ah0, bl);
                mma_f16(acc[1][nf], ah1, bl);
            }
        }

        // ---- frags -> s_out[oc][132] (conflict-free), then coalesced BN+store ----
        float* so = (float*)(smem + S_OUT);
        const int r0 = lane >> 2, c0 = (lane & 3) * 2;
#pragma unroll
        for (int mf = 0; mf < 2; ++mf)
#pragma unroll
            for (int nf = 0; nf < 8; ++nf) {
                const int px = wid * 32 + mf * 16 + r0;
                const int oc = nf * 8 + c0;
                so[oc * 132 + px]           = acc[mf][nf][0];
                so[(oc + 1) * 132 + px]     = acc[mf][nf][1];
                so[oc * 132 + px + 8]       = acc[mf][nf][2];
                so[(oc + 1) * 132 + px + 8] = acc[mf][nf][3];
            }
        __syncthreads();

        for (int i = tid; i < 64 * 32; i += 128) {
            const int oc = i >> 5, ch = i & 31;
            float4 v = *(float4*)(so + oc * 132 + ch * 4);
            const float b = s_bias[oc], sc = s_sc[oc], sh = s_sh[oc];
            v.x = fmaxf(v.x + b, 0.f) * sc + sh;
            v.y = fmaxf(v.y + b, 0.f) * sc + sh;
            v.z = fmaxf(v.z + b, 0.f) * sc + sh;
            v.w = fmaxf(v.w + b, 0.f) * sc + sh;
            *(float4*)(g_conv2 + ((size_t)oc * HH + y) * CS + x0 + ch * 4) = v;
        }
        // no trailing sync needed: next tile's first __syncthreads() protects smem
    }
}

// ---------------- integral image: vertical (two-pass segmented) ----------------
__global__ __launch_bounds__(192)
void vscanA_kernel()
{
    const int tx = threadIdx.x;
    const int seg = blockIdx.x;
    const int c = blockIdx.y;
    const float* src = g_conv2 + (size_t)c * HH * CS + tx * 4;
    const int y0 = seg * SEGH;

    float4 s = make_float4(0.f, 0.f, 0.f, 0.f);
#pragma unroll 1
    for (int ch = 0; ch < SEGH / 8; ++ch) {
        float4 v[8];
#pragma unroll
        for (int r = 0; r < 8; ++r)
            v[r] = *(const float4*)(src + (size_t)(y0 + ch * 8 + r) * CS);
#pragma unroll
        for (int r = 0; r < 8; ++r) {
            s.x += v[r].x; s.y += v[r].y; s.z += v[r].z; s.w += v[r].w;
        }
    }
    *(float4*)(g_segsum + ((size_t)c * NSEG + seg) * CS + tx * 4) = s;

    if (seg == 0) {
        *(float4*)(g_integ + (size_t)c * IW * RS + tx * 4) =
            make_float4(0.f, 0.f, 0.f, 0.f);
        if (tx == 0) g_integ[(size_t)c * IW * RS + 768] = 0.f;
    }
}

__global__ __launch_bounds__(192)
void vscanB_kernel()
{
    const int tx = threadIdx.x;
    const int seg = blockIdx.x;
    const int c = blockIdx.y;
    const float* src = g_conv2 + (size_t)c * HH * CS + tx * 4;
    float* dst = g_integ + (size_t)c * IW * RS + tx * 4;
    const int y0 = seg * SEGH;

    float4 run = make_float4(0.f, 0.f, 0.f, 0.f);
    for (int s = 0; s < seg; ++s) {
        float4 sv = *(const float4*)(g_segsum + ((size_t)c * NSEG + s) * CS + tx * 4);
        run.x += sv.x; run.y += sv.y; run.z += sv.z; run.w += sv.w;
    }

#pragma unroll 1
    for (int ch = 0; ch < SEGH / 8; ++ch) {
        float4 v[8];
#pragma unroll
        for (int r = 0; r < 8; ++r)
            v[r] = *(const float4*)(src + (size_t)(y0 + ch * 8 + r) * CS);
#pragma unroll
        for (int r = 0; r < 8; ++r) {
            run.x += v[r].x; run.y += v[r].y; run.z += v[r].z; run.w += v[r].w;
            *(float4*)(dst + (size_t)(1 + y0 + ch * 8 + r) * RS) = run;
        }
    }
}

// ---------------- integral image: horizontal ----------------
__global__ __launch_bounds__(256)
void hscan_kernel()
{
    const int warp = (blockIdx.x * blockDim.x + threadIdx.x) >> 5;
    const int lane = threadIdx.x & 31;
    if (warp >= C2N * HH) return;
    const int c = warp / HH;
    const int y = warp % HH + 1;
    float* row = g_integ + ((size_t)c * IW + y) * RS;

    float v[24];
#pragma unroll
    for (int k = 0; k < 24; ++k)
        v[k] = row[k * 32 + lane];

    float carry = 0.f;
#pragma unroll
    for (int k = 0; k < 24; ++k) {
#pragma unroll
        for (int d = 1; d < 32; d <<= 1) {
            float n = __shfl_up_sync(0xFFFFFFFFu, v[k], d);
            if (lane >= d) v[k] += n;
        }
        v[k] += carry;
        carry = __shfl_sync(0xFFFFFFFFu, v[k], 31);
    }

#pragma unroll
    for (int k = 0; k < 24; ++k)
        row[1 + k * 32 + lane] = v[k];
    if (lane == 0) row[0] = 0.f;
}

// ---------------- ROI 5x5 pooling via integral image ----------------
__global__ void pool_kernel(const int* __restrict__ boxes)
{
    const int n = blockIdx.x;
    __shared__ int sy0[5], sy1[5], sx0[5], sx1[5];
    const int tid = threadIdx.x;
    if (tid < 5) {
        const int xmin = boxes[n * 4 + 0];
        const int ymin = boxes[n * 4 + 1];
        const int xmax = boxes[n * 4 + 2];
        const int ymax = boxes[n * 4 + 3];
        const int bh = ymax - ymin;
        const int bw = xmax - xmin;
        sy0[tid] = ymin + tid * bh / 5;
        sy1[tid] = ymin + ((tid + 1) * bh + 4) / 5;
        sx0[tid] = xmin + tid * bw / 5;
        sx1[tid] = xmin + ((tid + 1) * bw + 4) / 5;
    }
    __syncthreads();
    for (int e = tid; e < FEAT; e += blockDim.x) {
        const int c = e / 25, ij = e % 25, i = ij / 5, j = ij % 5;
        const float* I = g_integ + (size_t)c * IW * RS;
        const int y0 = sy0[i], y1 = sy1[i], x0 = sx0[j], x1 = sx1[j];
        const float s = I[(size_t)y1 * RS + x1] - I[(size_t)y0 * RS + x1]
                      - I[(size_t)y1 * RS + x0] + I[(size_t)y0 * RS + x0];
        const float area = (float)((y1 - y0) * (x1 - x0));
        g_flat[(size_t)n * FEAT + e] = s / area;
    }
}

// ---------------- fc1: (512,1600) @ (1600,128)^T + relu ----------------
__global__ __launch_bounds__(128)
void fc1_kernel(const float* __restrict__ w, const float* __restrict__ b)
{
    __shared__ float sf[4][FEAT];
    const int nb0 = blockIdx.x * 4;
    const int tid = threadIdx.x;
    for (int i = tid; i < 4 * FEAT; i += 128)
        sf[i / FEAT][i % FEAT] = g_flat[(size_t)(nb0 + i / FEAT) * FEAT + i % FEAT];
    __syncthreads();

    float acc0 = 0.f, acc1 = 0.f, acc2 = 0.f, acc3 = 0.f;
    const float* wr = w + (size_t)tid * FEAT;
    for (int k = 0; k < FEAT; k += 4) {
        const float4 wv = *(const float4*)(wr + k);
        acc0 += sf[0][k] * wv.x + sf[0][k + 1] * wv.y + sf[0][k + 2] * wv.z + sf[0][k + 3] * wv.w;
        acc1 += sf[1][k] * wv.x + sf[1][k + 1] * wv.y + sf[1][k + 2] * wv.z + sf[1][k + 3] * wv.w;
        acc2 += sf[2][k] * wv.x + sf[2][k + 1] * wv.y + sf[2][k + 2] * wv.z + sf[2][k + 3] * wv.w;
        acc3 += sf[3][k] * wv.x + sf[3][k + 1] * wv.y + sf[3][k + 2] * wv.z + sf[3][k + 3] * wv.w;
    }
    const float bb = b[tid];
    float r0 = acc0 + bb, r1 = acc1 + bb, r2 = acc2 + bb, r3 = acc3 + bb;
    g_h1[(size_t)(nb0 + 0) * FC1N + tid] = r0 > 0.f ? r0 : 0.f;
    g_h1[(size_t)(nb0 + 1) * FC1N + tid] = r1 > 0.f ? r1 : 0.f;
    g_h1[(size_t)(nb0 + 2) * FC1N + tid] = r2 > 0.f ? r2 : 0.f;
    g_h1[(size_t)(nb0 + 3) * FC1N + tid] = r3 > 0.f ? r3 : 0.f;
}

// ---------------- fc2: (512,128) @ (128,4)^T ----------------
__global__ void fc2_kernel(const float* __restrict__ w, const float* __restrict__ bias,
                           float* __restrict__ out)
{
    const int t = blockIdx.x * blockDim.x + threadIdx.x;
    if (t >= NB * NCLS) return;
    const int n = t / NCLS, o = t % NCLS;
    const float* h  = g_h1 + (size_t)n * FC1N;
    const float* wr = w + (size_t)o * FC1N;
    float acc = 0.f;
#pragma unroll 8
    for (int k = 0; k < FC1N; ++k) acc += h[k] * wr[k];
    out[t] = acc + bias[o];
}

// ---------------- launch ----------------
extern "C" void kernel_launch(void* const* d_in, const int* in_sizes, int n_in,
                              void* d_out, int out_size)
{
    const float* image  = (const float*)d_in[0];
    const int*   boxes  = (const int*)d_in[1];
    const float* c1w    = (const float*)d_in[2];
    const float* c1b    = (const float*)d_in[3];
    const float* bn1g   = (const float*)d_in[4];
    const float* bn1b   = (const float*)d_in[5];
    const float* bn1m   = (const float*)d_in[6];
    const float* bn1v   = (const float*)d_in[7];
    const float* c2w    = (const float*)d_in[8];
    const float* c2b    = (const float*)d_in[9];
    const float* bn2g   = (const float*)d_in[10];
    const float* bn2b   = (const float*)d_in[11];
    const float* bn2m   = (const float*)d_in[12];
    const float* bn2v   = (const float*)d_in[13];
    const float* fc1w   = (const float*)d_in[14];
    const float* fc1b   = (const float*)d_in[15];
    const float* fc2w   = (const float*)d_in[16];
    const float* fc2b   = (const float*)d_in[17];
    float* out = (float*)d_out;

    cudaFuncSetAttribute((const void*)conv2_mma_kernel,
                         cudaFuncAttributeMaxDynamicSharedMemorySize, SMEM_CONV2);

    // slots 1-2: dummies so ncu's fixed capture slot (4th launch) lands on conv2
    dummy_kernel<<<1, 32>>>();
    dummy_kernel<<<1, 32>>>();

    // slot 3: conv1 (3 -> 32), writes g_act_hi/lo [y][x][ic] fp16
    conv1_kernel<<<dim3(24, 48, 2), dim3(32, 4)>>>(
        image, c1w, c1b, bn1g, bn1b, bn1m, bn1v);

    // slot 4 (PROFILED): conv2 via mma.sync fp16-split, writes g_conv2 fp32
    conv2_mma_kernel<<<148, 128, SMEM_CONV2>>>(
        c2w, c2b, bn2g, bn2b, bn2m, bn2v);

    // vertical cumsum: segmented two-pass (parallel, BW-bound)
    vscanA_kernel<<<dim3(NSEG, C2N), 192>>>();
    vscanB_kernel<<<dim3(NSEG, C2N), 192>>>();

    // horizontal cumsum (+1 column shift into final integral layout)
    hscan_kernel<<<(C2N * HH) / 8, 256>>>();

    // ROI pooling -> g_flat
    pool_kernel<<<NB, 256>>>(boxes);

    // fc1 -> g_h1 (relu)
    fc1_kernel<<<NB / 4, 128>>>(fc1w, fc1b);

    // fc2 -> out
    fc2_kernel<<<(NB * NCLS + 255) / 256, 256>>>(fc2w, fc2b, out);
}

// round 16
// speedup vs baseline: 2.2626x; 1.1921x over previous
#include <cuda_runtime.h>
#include <cuda_fp16.h>
#include <cstdint>

#define HH 768
#define WW 768
#define NB 512
#define C1N 32
#define C2N 64
#define IW 769            // logical integral image height/width (H+1)
#define RS 772            // padded integral row stride (16B aligned)
#define CS 768            // conv2 output row stride (compact, aligned)
#define FEAT 1600         // C2 * 5 * 5
#define FC1N 128
#define NCLS 4
#define NSEG 8            // vertical scan segments (768/96)
#define SEGH 96
#define NT2 (HH * 3)      // conv2 tiles: 768 rows x 3 x-tiles of 256 px

// conv2 smem layout (bytes). S_OUT aliases SI (input dead after MMA; sync guards).
#define SI_HI 0                       // 3 x 260 px x 80B
#define SI_LO 62400
#define SW_HI 124800                  // 9 taps x 64 oc x 80B
#define SW_LO 170880
#define S_BN  216960
#define SMEM_CONV2 217728
#define S_OUT 0                       // fp32 staging [64][260], aliases SI

// ---------------- scratch (no allocations allowed) ----------------
__device__ __half g_act_hi[HH * WW * C1N];   // conv1 out hi, [y][x][ic]
__device__ __half g_act_lo[HH * WW * C1N];   // conv1 out lo, [y][x][ic]
__device__ float g_conv2[C2N * HH * CS];     // conv2 output (64,768,768)
__device__ float g_integ[C2N * IW * RS];     // integral image (64,769,772)
__device__ float g_segsum[C2N * NSEG * CS];  // per-segment column sums
__device__ float g_flat[NB * FEAT];          // pooled features (512,1600)
__device__ float g_h1[NB * FC1N];            // fc1 output (512,128)

// ---------------- packed f32x2 helpers ----------------
typedef unsigned long long ull;

__device__ __forceinline__ ull ffma2(ull a, ull b, ull c) {
    ull d;
    asm("fma.rn.f32x2 %0, %1, %2, %3;" : "=l"(d) : "l"(a), "l"(b), "l"(c));
    return d;
}
__device__ __forceinline__ ull pack2(float lo, float hi) {
    ull r;
    asm("mov.b64 %0, {%1, %2};" : "=l"(r) : "f"(lo), "f"(hi));
    return r;
}
__device__ __forceinline__ void unpack2(ull v, float& lo, float& hi) {
    asm("mov.b64 {%0, %1}, %2;" : "=f"(lo), "=f"(hi) : "l"(v));
}

// ---------------- mma.sync / ldmatrix helpers (arch-agnostic PTX) ----------------
__device__ __forceinline__ uint32_t smem_to_u32(const void* p) {
    uint32_t a;
    asm("{ .reg .u64 t; cvta.to.shared.u64 t, %1; cvt.u32.u64 %0, t; }" : "=r"(a) : "l"(p));
    return a;
}
__device__ __forceinline__ void ldsm_x4(uint32_t* r, uint32_t addr) {
    asm volatile("ldmatrix.sync.aligned.m8n8.x4.shared.b16 {%0,%1,%2,%3}, [%4];"
                 : "=r"(r[0]), "=r"(r[1]), "=r"(r[2]), "=r"(r[3]) : "r"(addr));
}
__device__ __forceinline__ void ldsm_x2(uint32_t* r, uint32_t addr) {
    asm volatile("ldmatrix.sync.aligned.m8n8.x2.shared.b16 {%0,%1}, [%2];"
                 : "=r"(r[0]), "=r"(r[1]) : "r"(addr));
}
__device__ __forceinline__ void mma_f16(float* d, const uint32_t* a, const uint32_t* b) {
    asm volatile("mma.sync.aligned.m16n8k16.row.col.f32.f16.f16.f32 "
                 "{%0,%1,%2,%3}, {%4,%5,%6,%7}, {%8,%9}, {%0,%1,%2,%3};"
                 : "+f"(d[0]), "+f"(d[1]), "+f"(d[2]), "+f"(d[3])
                 : "r"(a[0]), "r"(a[1]), "r"(a[2]), "r"(a[3]), "r"(b[0]), "r"(b[1]));
}

// ---------------- profiling-slot dummy ----------------
__global__ void dummy_kernel() {}

// ---------------- conv1: fused conv3x3 + bias + relu + bn -> fp16 hi/lo [y][x][ic]
__global__ __launch_bounds__(128)
void conv1_kernel(const float* __restrict__ in,
                  const float* __restrict__ wgt,   // [32][3][3][3]
                  const float* __restrict__ bias,
                  const float* __restrict__ bng,
                  const float* __restrict__ bnb,
                  const float* __restrict__ bnm,
                  const float* __restrict__ bnv)
{
    constexpr int IC = 3, OCC = 16;
    __shared__ float s_in[IC * 18 * 34];
    __shared__ float s_w[9 * IC * OCC];

    const int tx = threadIdx.x, ty = threadIdx.y;
    const int tid = ty * 32 + tx;
    const int bx0 = blockIdx.x * 32;
    const int by0 = blockIdx.y * 16;
    const int ocBase = blockIdx.z * OCC;

    for (int idx = tid; idx < IC * 18 * 34; idx += 128) {
        int ic = idx / (18 * 34);
        int r  = idx % (18 * 34);
        int yy = r / 34, xx = r % 34;
        int gy = by0 + yy - 1, gx = bx0 + xx - 1;
        float v = 0.f;
        if (gy >= 0 && gy < HH && gx >= 0 && gx < WW)
            v = in[(ic * HH + gy) * WW + gx];
        s_in[idx] = v;
    }
    for (int idx = tid; idx < 9 * IC * OCC; idx += 128) {
        int tap = idx / (IC * OCC);
        int r   = idx % (IC * OCC);
        int ic  = r / OCC, oc = r % OCC;
        s_w[idx] = wgt[((ocBase + oc) * IC + ic) * 9 + tap];
    }
    __syncthreads();

    constexpr int OCP = OCC / 2;
    ull acc[OCP][4];
#pragma unroll
    for (int op = 0; op < OCP; ++op)
#pragma unroll
        for (int p = 0; p < 4; ++p) acc[op][p] = 0ull;

#pragma unroll
    for (int ic = 0; ic < IC; ++ic) {
        float v[6][3];
#pragma unroll
        for (int r = 0; r < 6; ++r)
#pragma unroll
            for (int q = 0; q < 3; ++q)
                v[r][q] = s_in[(ic * 18 + ty * 4 + r) * 34 + tx + q];
#pragma unroll
        for (int tap = 0; tap < 9; ++tap) {
            const int ky = tap / 3, kx = tap % 3;
            ull vv[4];
#pragma unroll
            for (int p = 0; p < 4; ++p)
                vv[p] = pack2(v[p + ky][kx], v[p + ky][kx]);
            const ull* wrow = (const ull*)&s_w[(tap * IC + ic) * OCC];
#pragma unroll
            for (int op = 0; op < OCP; ++op) {
                const ull w2 = wrow[op];
#pragma unroll
                for (int p = 0; p < 4; ++p)
                    acc[op][p] = ffma2(vv[p], w2, acc[op][p]);
            }
        }
    }

    float bb[OCC], scv[OCC], shv[OCC];
#pragma unroll
    for (int j = 0; j < OCC; ++j) {
        const int ocg = ocBase + j;
        bb[j]  = bias[ocg];
        scv[j] = bng[ocg] / sqrtf(bnv[ocg] + 1e-5f);
        shv[j] = bnb[ocg] - bnm[ocg] * scv[j];
    }

#pragma unroll
    for (int p = 0; p < 4; ++p) {
        float res[OCC];
#pragma unroll
        for (int op = 0; op < OCP; ++op) {
            float lo, hi;
            unpack2(acc[op][p], lo, hi);
            res[op * 2 + 0] = lo;
            res[op * 2 + 1] = hi;
        }
        uint32_t hw[8], lw[8];
#pragma unroll
        for (int j = 0; j < OCC; ++j) {
            float vv = res[j] + bb[j];
            vv = vv > 0.f ? vv : 0.f;
            vv = vv * scv[j] + shv[j];
            __half h = __float2half(vv);
            float rem = vv - __half2float(h);
            __half l = __float2half(rem);
            unsigned short hu = __half_as_ushort(h);
            unsigned short lu = __half_as_ushort(l);
            if (j & 1) {
                hw[j >> 1] |= ((uint32_t)hu) << 16;
                lw[j >> 1] |= ((uint32_t)lu) << 16;
            } else {
                hw[j >> 1] = hu;
                lw[j >> 1] = lu;
            }
        }
        const int gy = by0 + ty * 4 + p;
        const int gx = bx0 + tx;
        const size_t pix = (size_t)gy * WW + gx;
        uint4* dh = (uint4*)g_act_hi + pix * 4 + (ocBase >> 3);
        uint4* dl = (uint4*)g_act_lo + pix * 4 + (ocBase >> 3);
        dh[0] = make_uint4(hw[0], hw[1], hw[2], hw[3]);
        dh[1] = make_uint4(hw[4], hw[5], hw[6], hw[7]);
        dl[0] = make_uint4(lw[0], lw[1], lw[2], lw[3]);
        dl[1] = make_uint4(lw[4], lw[5], lw[6], lw[7]);
    }
}

// ---------------- conv2: mma.sync implicit GEMM (fp16 hi/lo split) ----------------
// Persistent 148 CTAs x 256 threads (8 warps, 2/SMSP). Tile = 256 px x 64 oc.
// Warp = 32 px (2 m-frags x 8 n-frags). Chains: hi*whi + lo*whi + hi*wlo.
__global__ __launch_bounds__(256, 1)
void conv2_mma_kernel(const float* __restrict__ wgt,   // [64][32][3][3]
                      const float* __restrict__ bias,
                      const float* __restrict__ bng,
                      const float* __restrict__ bnb,
                      const float* __restrict__ bnm,
                      const float* __restrict__ bnv)
{
    extern __shared__ char smem[];
    const int tid = threadIdx.x;
    const int wid = tid >> 5, lane = tid & 31;
    const uint32_t sb = smem_to_u32(smem);

    float* s_bias = (float*)(smem + S_BN);
    float* s_sc   = s_bias + 64;
    float* s_sh   = s_sc + 64;
    if (tid < 64) {
        float sc = bng[tid] / sqrtf(bnv[tid] + 1e-5f);
        s_bias[tid] = bias[tid];
        s_sc[tid]   = sc;
        s_sh[tid]   = bnb[tid] - bnm[tid] * sc;
    }

    // weights -> smem, [tap][oc] rows of 32 ic halves, 80B stride (conflict-free ldmatrix)
    for (int idx = tid; idx < 9 * 64 * 32; idx += 256) {
        const int t = idx / 2048, r = idx % 2048;
        const int oc = r >> 5, ic = r & 31;
        const float w = wgt[((size_t)(oc * 32 + ic)) * 9 + t];
        const __half h = __float2half(w);
        const __half l = __float2half(w - __half2float(h));
        *(__half*)(smem + SW_HI + (t * 64 + oc) * 80 + ic * 2) = h;
        *(__half*)(smem + SW_LO + (t * 64 + oc) * 80 + ic * 2) = l;
    }

    // lane-constant address components
    const int m16 = lane & 15, kh4 = lane >> 4;
    const uint32_t aHi0 = sb + SI_HI + (uint32_t)(wid * 32 + m16) * 80 + kh4 * 16;
    const uint32_t aHi1 = aHi0 + 16 * 80;
    const uint32_t aLo0 = aHi0 + (SI_LO - SI_HI);
    const uint32_t aLo1 = aHi1 + (SI_LO - SI_HI);
    const int n8 = lane & 7, bh8 = (lane >> 3) & 1;
    const uint32_t bHi = sb + SW_HI + (uint32_t)n8 * 80 + bh8 * 16;
    const uint32_t bLo = bHi + (SW_LO - SW_HI);

    __syncthreads();   // weights + BN ready; also guards SI alias below

    for (int tile = blockIdx.x; tile < NT2; tile += gridDim.x) {
        const int y = tile / 3, x0 = (tile % 3) * 256;

        // ---- stage input: rows y-1..y+1, px x0-1..x0+256 (258), hi+lo ----
        for (int i = tid; i < 3 * 258 * 4; i += 256) {
            const int q = i & 3, xl = (i >> 2) % 258, dy = (i >> 2) / 258;
            const int gy = y + dy - 1, gx = x0 - 1 + xl;
            uint4 vh = make_uint4(0u, 0u, 0u, 0u), vl = vh;
            if (gy >= 0 && gy < HH && gx >= 0 && gx < WW) {
                const size_t pix = (size_t)gy * WW + gx;
                vh = ((const uint4*)g_act_hi)[pix * 4 + q];
                vl = ((const uint4*)g_act_lo)[pix * 4 + q];
            }
            *(uint4*)(smem + SI_HI + (dy * 260 + xl) * 80 + q * 16) = vh;
            *(uint4*)(smem + SI_LO + (dy * 260 + xl) * 80 + q * 16) = vl;
        }
        __syncthreads();

        float acc[2][8][4];
#pragma unroll
        for (int mf = 0; mf < 2; ++mf)
#pragma unroll
            for (int nf = 0; nf < 8; ++nf)
#pragma unroll
                for (int e = 0; e < 4; ++e) acc[mf][nf][e] = 0.f;

#pragma unroll 1
        for (int ks = 0; ks < 18; ++ks) {
            const int tap = ks >> 1, ich = ks & 1;
            const int ky = tap / 3, kx = tap % 3;
            const uint32_t ao = (uint32_t)(ky * 260 + kx) * 80 + ich * 32;
            uint32_t ah0[4], ah1[4], al0[4], al1[4];
            ldsm_x4(ah0, aHi0 + ao);
            ldsm_x4(ah1, aHi1 + ao);
            ldsm_x4(al0, aLo0 + ao);
            ldsm_x4(al1, aLo1 + ao);
            const uint32_t bo = (uint32_t)(tap * 64) * 80 + ich * 32;
#pragma unroll
            for (int nf = 0; nf < 8; ++nf) {
                uint32_t bh[2], bl[2];
                ldsm_x2(bh, bHi + bo + nf * 8 * 80);
                ldsm_x2(bl, bLo + bo + nf * 8 * 80);
                mma_f16(acc[0][nf], ah0, bh);
                mma_f16(acc[1][nf], ah1, bh);
                mma_f16(acc[0][nf], al0, bh);
                mma_f16(acc[1][nf], al1, bh);
                mma_f16(acc[0][nf], ah0, bl);
                mma_f16(acc[1][nf], ah1, bl);
            }
        }
        __syncthreads();   // all ldsm reads of SI done before aliased S_OUT writes

        // ---- frags -> s_out[oc][260] (aliases SI), then coalesced BN+store ----
        float* so = (float*)(smem + S_OUT);
        const int r0 = lane >> 2, c0 = (lane & 3) * 2;
#pragma unroll
        for (int mf = 0; mf < 2; ++mf)
#pragma unroll
            for (int nf = 0; nf < 8; ++nf) {
                const int px = wid * 32 + mf * 16 + r0;
                const int oc = nf * 8 + c0;
                so[oc * 260 + px]           = acc[mf][nf][0];
                so[(oc + 1) * 260 + px]     = acc[mf][nf][1];
                so[oc * 260 + px + 8]       = acc[mf][nf][2];
                so[(oc + 1) * 260 + px + 8] = acc[mf][nf][3];
            }
        __syncthreads();

        for (int i = tid; i < 64 * 64; i += 256) {
            const int oc = i >> 6, ch = i & 63;
            float4 v = *(float4*)(so + oc * 260 + ch * 4);
            const float b = s_bias[oc], sc = s_sc[oc], sh = s_sh[oc];
            v.x = fmaxf(v.x + b, 0.f) * sc + sh;
            v.y = fmaxf(v.y + b, 0.f) * sc + sh;
            v.z = fmaxf(v.z + b, 0.f) * sc + sh;
            v.w = fmaxf(v.w + b, 0.f) * sc + sh;
            *(float4*)(g_conv2 + ((size_t)oc * HH + y) * CS + x0 + ch * 4) = v;
        }
        __syncthreads();   // epilogue reads done before next tile restages SI
    }
}

// ---------------- integral image: vertical (two-pass segmented) ----------------
__global__ __launch_bounds__(192)
void vscanA_kernel()
{
    const int tx = threadIdx.x;
    const int seg = blockIdx.x;
    const int c = blockIdx.y;
    const float* src = g_conv2 + (size_t)c * HH * CS + tx * 4;
    const int y0 = seg * SEGH;

    float4 s = make_float4(0.f, 0.f, 0.f, 0.f);
#pragma unroll 1
    for (int ch = 0; ch < SEGH / 8; ++ch) {
        float4 v[8];
#pragma unroll
        for (int r = 0; r < 8; ++r)
            v[r] = *(const float4*)(src + (size_t)(y0 + ch * 8 + r) * CS);
#pragma unroll
        for (int r = 0; r < 8; ++r) {
            s.x += v[r].x; s.y += v[r].y; s.z += v[r].z; s.w += v[r].w;
        }
    }
    *(float4*)(g_segsum + ((size_t)c * NSEG + seg) * CS + tx * 4) = s;

    if (seg == 0) {
        *(float4*)(g_integ + (size_t)c * IW * RS + tx * 4) =
            make_float4(0.f, 0.f, 0.f, 0.f);
        if (tx == 0) g_integ[(size_t)c * IW * RS + 768] = 0.f;
    }
}

__global__ __launch_bounds__(192)
void vscanB_kernel()
{
    const int tx = threadIdx.x;
    const int seg = blockIdx.x;
    const int c = blockIdx.y;
    const float* src = g_conv2 + (size_t)c * HH * CS + tx * 4;
    float* dst = g_integ + (size_t)c * IW * RS + tx * 4;
    const int y0 = seg * SEGH;

    float4 run = make_float4(0.f, 0.f, 0.f, 0.f);
    for (int s = 0; s < seg; ++s) {
        float4 sv = *(const float4*)(g_segsum + ((size_t)c * NSEG + s) * CS + tx * 4);
        run.x += sv.x; run.y += sv.y; run.z += sv.z; run.w += sv.w;
    }

#pragma unroll 1
    for (int ch = 0; ch < SEGH / 8; ++ch) {
        float4 v[8];
#pragma unroll
        for (int r = 0; r < 8; ++r)
            v[r] = *(const float4*)(src + (size_t)(y0 + ch * 8 + r) * CS);
#pragma unroll
        for (int r = 0; r < 8; ++r) {
            run.x += v[r].x; run.y += v[r].y; run.z += v[r].z; run.w += v[r].w;
            *(float4*)(dst + (size_t)(1 + y0 + ch * 8 + r) * RS) = run;
        }
    }
}

// ---------------- integral image: horizontal ----------------
__global__ __launch_bounds__(256)
void hscan_kernel()
{
    const int warp = (blockIdx.x * blockDim.x + threadIdx.x) >> 5;
    const int lane = threadIdx.x & 31;
    if (warp >= C2N * HH) return;
    const int c = warp / HH;
    const int y = warp % HH + 1;
    float* row = g_integ + ((size_t)c * IW + y) * RS;

    float v[24];
#pragma unroll
    for (int k = 0; k < 24; ++k)
        v[k] = row[k * 32 + lane];

    float carry = 0.f;
#pragma unroll
    for (int k = 0; k < 24; ++k) {
#pragma unroll
        for (int d = 1; d < 32; d <<= 1) {
            float n = __shfl_up_sync(0xFFFFFFFFu, v[k], d);
            if (lane >= d) v[k] += n;
        }
        v[k] += carry;
        carry = __shfl_sync(0xFFFFFFFFu, v[k], 31);
    }

#pragma unroll
    for (int k = 0; k < 24; ++k)
        row[1 + k * 32 + lane] = v[k];
    if (lane == 0) row[0] = 0.f;
}

// ---------------- ROI 5x5 pooling via integral image ----------------
__global__ void pool_kernel(const int* __restrict__ boxes)
{
    const int n = blockIdx.x;
    __shared__ int sy0[5], sy1[5], sx0[5], sx1[5];
    const int tid = threadIdx.x;
    if (tid < 5) {
        const int xmin = boxes[n * 4 + 0];
        const int ymin = boxes[n * 4 + 1];
        const int xmax = boxes[n * 4 + 2];
        const int ymax = boxes[n * 4 + 3];
        const int bh = ymax - ymin;
        const int bw = xmax - xmin;
        sy0[tid] = ymin + tid * bh / 5;
        sy1[tid] = ymin + ((tid + 1) * bh + 4) / 5;
        sx0[tid] = xmin + tid * bw / 5;
        sx1[tid] = xmin + ((tid + 1) * bw + 4) / 5;
    }
    __syncthreads();
    for (int e = tid; e < FEAT; e += blockDim.x) {
        const int c = e / 25, ij = e % 25, i = ij / 5, j = ij % 5;
        const float* I = g_integ + (size_t)c * IW * RS;
        const int y0 = sy0[i], y1 = sy1[i], x0 = sx0[j], x1 = sx1[j];
        const float s = I[(size_t)y1 * RS + x1] - I[(size_t)y0 * RS + x1]
                      - I[(size_t)y1 * RS + x0] + I[(size_t)y0 * RS + x0];
        const float area = (float)((y1 - y0) * (x1 - x0));
        g_flat[(size_t)n * FEAT + e] = s / area;
    }
}

// ---------------- fc1: (512,1600) @ (1600,128)^T + relu ----------------
__global__ __launch_bounds__(128)
void fc1_kernel(const float* __restrict__ w, const float* __restrict__ b)
{
    __shared__ float sf[4][FEAT];
    const int nb0 = blockIdx.x * 4;
    const int tid = threadIdx.x;
    for (int i = tid; i < 4 * FEAT; i += 128)
        sf[i / FEAT][i % FEAT] = g_flat[(size_t)(nb0 + i / FEAT) * FEAT + i % FEAT];
    __syncthreads();

    float acc0 = 0.f, acc1 = 0.f, acc2 = 0.f, acc3 = 0.f;
    const float* wr = w + (size_t)tid * FEAT;
    for (int k = 0; k < FEAT; k += 4) {
        const float4 wv = *(const float4*)(wr + k);
        acc0 += sf[0][k] * wv.x + sf[0][k + 1] * wv.y + sf[0][k + 2] * wv.z + sf[0][k + 3] * wv.w;
        acc1 += sf[1][k] * wv.x + sf[1][k + 1] * wv.y + sf[1][k + 2] * wv.z + sf[1][k + 3] * wv.w;
        acc2 += sf[2][k] * wv.x + sf[2][k + 1] * wv.y + sf[2][k + 2] * wv.z + sf[2][k + 3] * wv.w;
        acc3 += sf[3][k] * wv.x + sf[3][k + 1] * wv.y + sf[3][k + 2] * wv.z + sf[3][k + 3] * wv.w;
    }
    const float bb = b[tid];
    float r0 = acc0 + bb, r1 = acc1 + bb, r2 = acc2 + bb, r3 = acc3 + bb;
    g_h1[(size_t)(nb0 + 0) * FC1N + tid] = r0 > 0.f ? r0 : 0.f;
    g_h1[(size_t)(nb0 + 1) * FC1N + tid] = r1 > 0.f ? r1 : 0.f;
    g_h1[(size_t)(nb0 + 2) * FC1N + tid] = r2 > 0.f ? r2 : 0.f;
    g_h1[(size_t)(nb0 + 3) * FC1N + tid] = r3 > 0.f ? r3 : 0.f;
}

// ---------------- fc2: (512,128) @ (128,4)^T ----------------
__global__ void fc2_kernel(const float* __restrict__ w, const float* __restrict__ bias,
                           float* __restrict__ out)
{
    const int t = blockIdx.x * blockDim.x + threadIdx.x;
    if (t >= NB * NCLS) return;
    const int n = t / NCLS, o = t % NCLS;
    const float* h  = g_h1 + (size_t)n * FC1N;
    const float* wr = w + (size_t)o * FC1N;
    float acc = 0.f;
#pragma unroll 8
    for (int k = 0; k < FC1N; ++k) acc += h[k] * wr[k];
    out[t] = acc + bias[o];
}

// ---------------- launch ----------------
extern "C" void kernel_launch(void* const* d_in, const int* in_sizes, int n_in,
                              void* d_out, int out_size)
{
    const float* image  = (const float*)d_in[0];
    const int*   boxes  = (const int*)d_in[1];
    const float* c1w    = (const float*)d_in[2];
    const float* c1b    = (const float*)d_in[3];
    const float* bn1g   = (const float*)d_in[4];
    const float* bn1b   = (const float*)d_in[5];
    const float* bn1m   = (const float*)d_in[6];
    const float* bn1v   = (const float*)d_in[7];
    const float* c2w    = (const float*)d_in[8];
    const float* c2b    = (const float*)d_in[9];
    const float* bn2g   = (const float*)d_in[10];
    const float* bn2b   = (const float*)d_in[11];
    const float* bn2m   = (const float*)d_in[12];
    const float* bn2v   = (const float*)d_in[13];
    const float* fc1w   = (const float*)d_in[14];
    const float* fc1b   = (const float*)d_in[15];
    const float* fc2w   = (const float*)d_in[16];
    const float* fc2b   = (const float*)d_in[17];
    float* out = (float*)d_out;

    cudaFuncSetAttribute((const void*)conv2_mma_kernel,
                         cudaFuncAttributeMaxDynamicSharedMemorySize, SMEM_CONV2);

    // slots 1-2: dummies so ncu's fixed capture slot (4th launch) lands on conv2
    dummy_kernel<<<1, 32>>>();
    dummy_kernel<<<1, 32>>>();

    // slot 3: conv1 (3 -> 32), writes g_act_hi/lo [y][x][ic] fp16
    conv1_kernel<<<dim3(24, 48, 2), dim3(32, 4)>>>(
        image, c1w, c1b, bn1g, bn1b, bn1m, bn1v);

    // slot 4 (PROFILED): conv2 via mma.sync fp16-split, 8 warps, writes g_conv2 fp32
    conv2_mma_kernel<<<148, 256, SMEM_CONV2>>>(
        c2w, c2b, bn2g, bn2b, bn2m, bn2v);

    // vertical cumsum: segmented two-pass (parallel, BW-bound)
    vscanA_kernel<<<dim3(NSEG, C2N), 192>>>();
    vscanB_kernel<<<dim3(NSEG, C2N), 192>>>();

    // horizontal cumsum (+1 column shift into final integral layout)
    hscan_kernel<<<(C2N * HH) / 8, 256>>>();

    // ROI pooling -> g_flat
    pool_kernel<<<NB, 256>>>(boxes);

    // fc1 -> g_h1 (relu)
    fc1_kernel<<<NB / 4, 128>>>(fc1w, fc1b);

    // fc2 -> out
    fc2_kernel<<<(NB * NCLS + 255) / 256, 256>>>(fc2w, fc2b, out);
}